// round 3
// baseline (speedup 1.0000x reference)
#include <cuda_runtime.h>
#include <math.h>
#include <stdint.h>

// Problem constants (fixed by setup_inputs)
#define Bc   2
#define Tc   2048
#define Cc   1024
#define NH   16
#define HD   64
#define Mtot (Bc * Tc)        // 4096
#define N1   (3 * Cc)         // 3072
#define Kc   Cc               // 1024
#define Rr   16
#define LORA_SCALE (1.0f / 16.0f)

// Scratch (device globals: allocation-free rule)
__device__ float g_qkv[Mtot * N1];    // 48 MB (tf32-rounded)
__device__ float g_y[Mtot * Cc];      // 16 MB (tf32-rounded)
__device__ float g_xa[Mtot * Rr];
__device__ float g_ya[Mtot * Rr];
__device__ float g_xc[Mtot * Kc];     // 16 MB x (tf32)
__device__ float g_w1c[N1 * Kc];      // 12 MB w_attn (tf32)
__device__ float g_w2c[Cc * Kc];      //  4 MB w_proj (tf32)
__device__ float g_lb1c[N1 * Rr];     // lora_b_attn * scale (tf32)
__device__ float g_lb2c[Cc * Rr];     // lora_b_proj * scale (tf32)

// ---------------------------------------------------------------------------
// helpers
// ---------------------------------------------------------------------------
__device__ __forceinline__ unsigned f2t(float f) {
    unsigned u;
    asm("cvt.rna.tf32.f32 %0, %1;" : "=r"(u) : "f"(f));
    return u;
}
__device__ __forceinline__ float f2tf(float f) { return __uint_as_float(f2t(f)); }

__device__ __forceinline__ void mma_tf32(float* d, const unsigned* a,
                                         unsigned b0, unsigned b1) {
    asm volatile(
        "mma.sync.aligned.m16n8k8.row.col.f32.tf32.tf32.f32 "
        "{%0,%1,%2,%3},{%4,%5,%6,%7},{%8,%9},{%0,%1,%2,%3};\n"
        : "+f"(d[0]), "+f"(d[1]), "+f"(d[2]), "+f"(d[3])
        : "r"(a[0]), "r"(a[1]), "r"(a[2]), "r"(a[3]), "r"(b0), "r"(b1));
}

__device__ __forceinline__ uint32_t smem_u32(const void* p) {
    return (uint32_t)__cvta_generic_to_shared(p);
}
__device__ __forceinline__ void cp16(uint32_t dst, const void* src) {
    asm volatile("cp.async.ca.shared.global [%0], [%1], 16;" :: "r"(dst), "l"(src));
}
__device__ __forceinline__ void cp_commit() {
    asm volatile("cp.async.commit_group;");
}
template <int N> __device__ __forceinline__ void cp_wait() {
    asm volatile("cp.async.wait_group %0;" :: "n"(N));
}

// ---------------------------------------------------------------------------
// prep: tf32-round x, w_attn, w_proj; tf32-round scaled lora_b's.
// float4 grid-stride over concatenated regions.
// ---------------------------------------------------------------------------
#define NX4   (Mtot * Kc / 4)
#define NW14  (N1 * Kc / 4)
#define NW24  (Cc * Kc / 4)
#define NL14  (N1 * Rr / 4)
#define NL24  (Cc * Rr / 4)
#define NTOT4 (NX4 + NW14 + NW24 + NL14 + NL24)

__global__ __launch_bounds__(256)
void prep_kernel(const float4* __restrict__ x,  const float4* __restrict__ w1,
                 const float4* __restrict__ w2, const float4* __restrict__ l1,
                 const float4* __restrict__ l2,
                 float4* __restrict__ xc,  float4* __restrict__ w1c,
                 float4* __restrict__ w2c, float4* __restrict__ l1c,
                 float4* __restrict__ l2c)
{
    for (int i = blockIdx.x * blockDim.x + threadIdx.x; i < NTOT4;
         i += gridDim.x * blockDim.x) {
        float4 v; float4* dst; float s = 1.f;
        if (i < NX4)                          { v = x[i];                          dst = xc  + i; }
        else if (i < NX4 + NW14)              { v = w1[i - NX4];                   dst = w1c + (i - NX4); }
        else if (i < NX4 + NW14 + NW24)       { v = w2[i - NX4 - NW14];            dst = w2c + (i - NX4 - NW14); }
        else if (i < NX4 + NW14 + NW24 + NL14){ v = l1[i - NX4 - NW14 - NW24];     dst = l1c + (i - NX4 - NW14 - NW24); s = LORA_SCALE; }
        else                                  { v = l2[i - NX4 - NW14 - NW24 - NL14]; dst = l2c + (i - NX4 - NW14 - NW24 - NL14); s = LORA_SCALE; }
        float4 o;
        o.x = f2tf(v.x * s); o.y = f2tf(v.y * s);
        o.z = f2tf(v.z * s); o.w = f2tf(v.w * s);
        *dst = o;
    }
}

// ---------------------------------------------------------------------------
// LoRA A projection: XA[m,r] = sum_k X[m,k] * A[r,k]; writes tf32-rounded.
// ---------------------------------------------------------------------------
__global__ __launch_bounds__(256)
void lora_a_kernel(const float* __restrict__ X,
                   const float* __restrict__ Aw,
                   float* __restrict__ XA)
{
    const int lane = threadIdx.x & 31;
    const int w    = threadIdx.x >> 5;
    const int m    = blockIdx.x * 8 + w;

    float acc[Rr];
#pragma unroll
    for (int r = 0; r < Rr; r++) acc[r] = 0.f;

    const float* xr = X + (size_t)m * Kc;
#pragma unroll
    for (int it = 0; it < 8; it++) {
        int k = (it * 32 + lane) * 4;
        float4 xv = *(const float4*)&xr[k];
#pragma unroll
        for (int r = 0; r < Rr; r++) {
            float4 av = *(const float4*)&Aw[r * Kc + k];
            acc[r] += xv.x * av.x + xv.y * av.y + xv.z * av.z + xv.w * av.w;
        }
    }
#pragma unroll
    for (int r = 0; r < Rr; r++) {
        float v = acc[r];
#pragma unroll
        for (int off = 16; off; off >>= 1) v += __shfl_xor_sync(0xffffffffu, v, off);
        acc[r] = f2tf(v);
    }
    if (lane == 0) {
        float4* dst = (float4*)&XA[(size_t)m * Rr];
        dst[0] = make_float4(acc[0],  acc[1],  acc[2],  acc[3]);
        dst[1] = make_float4(acc[4],  acc[5],  acc[6],  acc[7]);
        dst[2] = make_float4(acc[8],  acc[9],  acc[10], acc[11]);
        dst[3] = make_float4(acc[12], acc[13], acc[14], acc[15]);
    }
}

// ---------------------------------------------------------------------------
// tf32 GEMM, cp.async double-buffered, LoRA folded as final K-stage:
//   out = [A | XA] @ [W | LBs]^T + bias
// Inputs already tf32. Block 128 x BN (BN=256 or 128), BK=32, 256 threads,
// 8 warps (2 in M x 4 in N), warp tile 64 x (BN/4).
// smem strides padded to 36 floats (conflict-free fragment reads, 16B align).
// ---------------------------------------------------------------------------
#define GBK 32
#define GSTR 36

template <int BN, bool ROUND>
__global__ __launch_bounds__(256)
void gemm_lora_tc(const float* __restrict__ A, const float* __restrict__ W,
                  const float* __restrict__ bias, const float* __restrict__ XA,
                  const float* __restrict__ LBs, float* __restrict__ out, int N)
{
    constexpr int NT = BN / 32;                 // n-tiles per warp (8 or 4)
    extern __shared__ float sm[];
    float* sA = sm;                             // [2][128][GSTR]
    float* sW = sm + 2 * 128 * GSTR;            // [2][BN][GSTR]

    const int tid  = threadIdx.x;
    const int row0 = blockIdx.y * 128;
    const int col0 = blockIdx.x * BN;
    const int lane = tid & 31, wid = tid >> 5;
    const int wm = (wid >> 2) * 64;
    const int wn = (wid & 3) * (BN / 4);
    const int g  = lane >> 2, tq = lane & 3;

    // load mapping
    const int arow = tid >> 1;
    const int akb  = (tid & 1) * 16;

    float acc[4][NT][4];
#pragma unroll
    for (int mt = 0; mt < 4; mt++)
#pragma unroll
        for (int nt = 0; nt < NT; nt++)
#pragma unroll
            for (int i = 0; i < 4; i++) acc[mt][nt][i] = 0.f;

    const int NMAIN = Kc / GBK;     // 32
    const int NST   = NMAIN + 1;    // + LoRA stage

    auto load_main = [&](int s, int buf) {
        const float* pa = A + (size_t)(row0 + arow) * Kc + s * GBK + akb;
        uint32_t da = smem_u32(&sA[(buf * 128 + arow) * GSTR + akb]);
        cp16(da,      pa);     cp16(da + 16, pa + 4);
        cp16(da + 32, pa + 8); cp16(da + 48, pa + 12);
        if (BN == 256) {
            const float* pw = W + (size_t)(col0 + tid) * Kc + s * GBK;
            uint32_t dw = smem_u32(&sW[(buf * BN + tid) * GSTR]);
#pragma unroll
            for (int c = 0; c < 8; c++) cp16(dw + 16 * c, pw + 4 * c);
        } else {
            const float* pw = W + (size_t)(col0 + arow) * Kc + s * GBK + akb;
            uint32_t dw = smem_u32(&sW[(buf * BN + arow) * GSTR + akb]);
            cp16(dw,      pw);     cp16(dw + 16, pw + 4);
            cp16(dw + 32, pw + 8); cp16(dw + 48, pw + 12);
        }
    };
    auto load_lora = [&](int buf) {
        const int kb2 = (tid & 1) * 8;
        const float* pa = XA + (size_t)(row0 + arow) * Rr + kb2;
        uint32_t da = smem_u32(&sA[(buf * 128 + arow) * GSTR + kb2]);
        cp16(da, pa); cp16(da + 16, pa + 4);
        if (BN == 256) {
            const float* pw = LBs + (size_t)(col0 + tid) * Rr;
            uint32_t dw = smem_u32(&sW[(buf * BN + tid) * GSTR]);
#pragma unroll
            for (int c = 0; c < 4; c++) cp16(dw + 16 * c, pw + 4 * c);
        } else {
            const float* pw = LBs + (size_t)(col0 + arow) * Rr + kb2;
            uint32_t dw = smem_u32(&sW[(buf * BN + arow) * GSTR + kb2]);
            cp16(dw, pw); cp16(dw + 16, pw + 4);
        }
    };
    auto compute = [&](int buf, int nk8) {
        const float* bA = sA + (size_t)buf * 128 * GSTR;
        const float* bW = sW + (size_t)buf * BN * GSTR;
        for (int k8 = 0; k8 < nk8; k8++) {
            const int k = k8 * 8;
            unsigned af[4][4], bf[NT][2];
#pragma unroll
            for (int mt = 0; mt < 4; mt++) {
                const int r0 = wm + mt * 16;
                af[mt][0] = __float_as_uint(bA[(r0 + g) * GSTR + k + tq]);
                af[mt][1] = __float_as_uint(bA[(r0 + g + 8) * GSTR + k + tq]);
                af[mt][2] = __float_as_uint(bA[(r0 + g) * GSTR + k + tq + 4]);
                af[mt][3] = __float_as_uint(bA[(r0 + g + 8) * GSTR + k + tq + 4]);
            }
#pragma unroll
            for (int nt = 0; nt < NT; nt++) {
                const int c0 = wn + nt * 8;
                bf[nt][0] = __float_as_uint(bW[(c0 + g) * GSTR + k + tq]);
                bf[nt][1] = __float_as_uint(bW[(c0 + g) * GSTR + k + tq + 4]);
            }
#pragma unroll
            for (int mt = 0; mt < 4; mt++)
#pragma unroll
                for (int nt = 0; nt < NT; nt++)
                    mma_tf32(acc[mt][nt], af[mt], bf[nt][0], bf[nt][1]);
        }
    };

    load_main(0, 0);
    cp_commit();

    for (int s = 0; s < NST; s++) {
        const int cur = s & 1;
        const bool hn = (s + 1 < NST);
        if (hn) {
            if (s + 1 < NMAIN) load_main(s + 1, cur ^ 1);
            else               load_lora(cur ^ 1);
            cp_commit();
            cp_wait<1>();
        } else {
            cp_wait<0>();
        }
        __syncthreads();                 // cur visible to all
        compute(cur, (s < NMAIN) ? 4 : 2);
        __syncthreads();                 // all done reading cur
    }

    // epilogue: bias, write (optionally tf32-rounded)
#pragma unroll
    for (int nt = 0; nt < NT; nt++) {
        const int c = col0 + wn + nt * 8 + 2 * tq;
        const float b0 = bias[c], b1 = bias[c + 1];
#pragma unroll
        for (int mt = 0; mt < 4; mt++) {
            const int r = row0 + wm + mt * 16 + g;
            float2 lo, hi;
            if (ROUND) {
                lo.x = f2tf(acc[mt][nt][0] + b0); lo.y = f2tf(acc[mt][nt][1] + b1);
                hi.x = f2tf(acc[mt][nt][2] + b0); hi.y = f2tf(acc[mt][nt][3] + b1);
            } else {
                lo.x = acc[mt][nt][0] + b0; lo.y = acc[mt][nt][1] + b1;
                hi.x = acc[mt][nt][2] + b0; hi.y = acc[mt][nt][3] + b1;
            }
            *(float2*)&out[(size_t)r * N + c] = lo;
            *(float2*)&out[(size_t)(r + 8) * N + c] = hi;
        }
    }
}

#define GEMM_SMEM(BN) ((2 * 128 * GSTR + 2 * (BN) * GSTR) * 4)

// ---------------------------------------------------------------------------
// Flash attention, tf32 mma, cp.async double-buffered K/V.
// qkv is tf32-rounded; scale 0.125 is exact in tf32 so no converts needed
// except for P (exp output). Block = 64 q-rows of one (b,h), 128 threads.
// ---------------------------------------------------------------------------
#define KS_STRIDE 68
#define VS_STRIDE 72
#define PS_STRIDE 68
#define ATTN_SMEM ((2 * 64 * KS_STRIDE + 2 * 64 * VS_STRIDE + 64 * PS_STRIDE) * 4)

__global__ __launch_bounds__(128)
void attn_tc(const float* __restrict__ qkv, float* __restrict__ Y)
{
    extern __shared__ float sm[];
    float* Ks = sm;                                   // [2][64][68]
    float* Vs = sm + 2 * 64 * KS_STRIDE;              // [2][64][72]
    float* Ps = sm + 2 * 64 * KS_STRIDE + 2 * 64 * VS_STRIDE;  // [64][68]

    const int qb  = blockIdx.x;
    const int bh  = blockIdx.y;
    const int b   = bh >> 4;
    const int h   = bh & 15;
    const int tid = threadIdx.x;
    const int lane = tid & 31, wid = tid >> 5;
    const int wm  = wid * 16;
    const int g   = lane >> 2, tq = lane & 3;
    const int qg0 = qb * 64;

    const float* qptr = qkv + (size_t)(b * Tc) * N1 + h * HD;
    const float* kptr = qptr + Cc;
    const float* vptr = qptr + 2 * Cc;

    // KV tile load mapping: row = tid>>1, 8 chunks of 16B per tensor
    const int krow  = tid >> 1;
    const int kcol0 = (tid & 1) * 32;

    auto load_kv = [&](int jt, int buf) {
        const size_t gro = (size_t)(jt * 64 + krow) * N1 + kcol0;
        uint32_t dk = smem_u32(&Ks[(buf * 64 + krow) * KS_STRIDE + kcol0]);
        uint32_t dv = smem_u32(&Vs[(buf * 64 + krow) * VS_STRIDE + kcol0]);
        const float* pk = kptr + gro;
        const float* pv = vptr + gro;
#pragma unroll
        for (int c = 0; c < 8; c++) {
            cp16(dk + 16 * c, pk + 4 * c);
            cp16(dv + 16 * c, pv + 4 * c);
        }
    };

    // stage Q tile into Ps, extract scaled fragments (0.125 exact in tf32)
#pragma unroll
    for (int u = 0; u < 8; u++) {
        int idx = tid + u * 128;
        int r = idx >> 4, c4 = (idx & 15) * 4;
        *(float4*)&Ps[r * PS_STRIDE + c4] =
            *(const float4*)&qptr[(size_t)(qg0 + r) * N1 + c4];
    }

    load_kv(0, 0);
    cp_commit();
    __syncthreads();

    unsigned qa[8][4];
#pragma unroll
    for (int kb = 0; kb < 8; kb++) {
        qa[kb][0] = __float_as_uint(Ps[(wm + g) * PS_STRIDE + kb * 8 + tq] * 0.125f);
        qa[kb][1] = __float_as_uint(Ps[(wm + g + 8) * PS_STRIDE + kb * 8 + tq] * 0.125f);
        qa[kb][2] = __float_as_uint(Ps[(wm + g) * PS_STRIDE + kb * 8 + tq + 4] * 0.125f);
        qa[kb][3] = __float_as_uint(Ps[(wm + g + 8) * PS_STRIDE + kb * 8 + tq + 4] * 0.125f);
    }
    __syncthreads();   // everyone has Q frags before Ps is reused for P

    float o[8][4];
#pragma unroll
    for (int nt = 0; nt < 8; nt++)
#pragma unroll
        for (int i = 0; i < 4; i++) o[nt][i] = 0.f;
    float m_lo = -INFINITY, m_hi = -INFINITY, l_lo = 0.f, l_hi = 0.f;

    const int r_lo = qg0 + wm + g;
    const int r_hi = r_lo + 8;

    for (int jt = 0; jt <= qb; jt++) {
        const int cur = jt & 1;
        const bool hn = (jt + 1 <= qb);
        if (hn) { load_kv(jt + 1, cur ^ 1); cp_commit(); cp_wait<1>(); }
        else    { cp_wait<0>(); }
        __syncthreads();

        const float* bK = Ks + (size_t)cur * 64 * KS_STRIDE;
        const float* bV = Vs + (size_t)cur * 64 * VS_STRIDE;

        // S = Q @ K^T (scaled)
        float sc[8][4];
#pragma unroll
        for (int nt = 0; nt < 8; nt++) {
#pragma unroll
            for (int i = 0; i < 4; i++) sc[nt][i] = 0.f;
#pragma unroll
            for (int kb = 0; kb < 8; kb++) {
                unsigned b0 = __float_as_uint(bK[(nt * 8 + g) * KS_STRIDE + kb * 8 + tq]);
                unsigned b1 = __float_as_uint(bK[(nt * 8 + g) * KS_STRIDE + kb * 8 + tq + 4]);
                mma_tf32(sc[nt], qa[kb], b0, b1);
            }
        }

        // causal mask on the diagonal tile
        if (jt == qb) {
#pragma unroll
            for (int nt = 0; nt < 8; nt++) {
                const int c = qg0 + nt * 8 + 2 * tq;
                if (c     > r_lo) sc[nt][0] = -INFINITY;
                if (c + 1 > r_lo) sc[nt][1] = -INFINITY;
                if (c     > r_hi) sc[nt][2] = -INFINITY;
                if (c + 1 > r_hi) sc[nt][3] = -INFINITY;
            }
        }

        // online softmax
        float tmax_lo = -INFINITY, tmax_hi = -INFINITY;
#pragma unroll
        for (int nt = 0; nt < 8; nt++) {
            tmax_lo = fmaxf(tmax_lo, fmaxf(sc[nt][0], sc[nt][1]));
            tmax_hi = fmaxf(tmax_hi, fmaxf(sc[nt][2], sc[nt][3]));
        }
        tmax_lo = fmaxf(tmax_lo, __shfl_xor_sync(0xffffffffu, tmax_lo, 1));
        tmax_lo = fmaxf(tmax_lo, __shfl_xor_sync(0xffffffffu, tmax_lo, 2));
        tmax_hi = fmaxf(tmax_hi, __shfl_xor_sync(0xffffffffu, tmax_hi, 1));
        tmax_hi = fmaxf(tmax_hi, __shfl_xor_sync(0xffffffffu, tmax_hi, 2));

        const float mn_lo = fmaxf(m_lo, tmax_lo);
        const float mn_hi = fmaxf(m_hi, tmax_hi);
        const float corr_lo = __expf(m_lo - mn_lo);
        const float corr_hi = __expf(m_hi - mn_hi);
        m_lo = mn_lo; m_hi = mn_hi;

        float ls_lo = 0.f, ls_hi = 0.f;
#pragma unroll
        for (int nt = 0; nt < 8; nt++) {
            float p0 = __expf(sc[nt][0] - mn_lo);
            float p1 = __expf(sc[nt][1] - mn_lo);
            float p2 = __expf(sc[nt][2] - mn_hi);
            float p3 = __expf(sc[nt][3] - mn_hi);
            ls_lo += p0 + p1;
            ls_hi += p2 + p3;
            float2 v0; v0.x = f2tf(p0); v0.y = f2tf(p1);
            *(float2*)&Ps[(wm + g) * PS_STRIDE + nt * 8 + 2 * tq] = v0;
            float2 v1; v1.x = f2tf(p2); v1.y = f2tf(p3);
            *(float2*)&Ps[(wm + g + 8) * PS_STRIDE + nt * 8 + 2 * tq] = v1;
        }
        ls_lo += __shfl_xor_sync(0xffffffffu, ls_lo, 1);
        ls_lo += __shfl_xor_sync(0xffffffffu, ls_lo, 2);
        ls_hi += __shfl_xor_sync(0xffffffffu, ls_hi, 1);
        ls_hi += __shfl_xor_sync(0xffffffffu, ls_hi, 2);
        l_lo = l_lo * corr_lo + ls_lo;
        l_hi = l_hi * corr_hi + ls_hi;

#pragma unroll
        for (int nt = 0; nt < 8; nt++) {
            o[nt][0] *= corr_lo; o[nt][1] *= corr_lo;
            o[nt][2] *= corr_hi; o[nt][3] *= corr_hi;
        }
        __syncwarp();   // P rows are warp-private; warp-level fence suffices

        // O += P @ V
#pragma unroll
        for (int kb = 0; kb < 8; kb++) {
            unsigned pa[4];
            pa[0] = __float_as_uint(Ps[(wm + g) * PS_STRIDE + kb * 8 + tq]);
            pa[1] = __float_as_uint(Ps[(wm + g + 8) * PS_STRIDE + kb * 8 + tq]);
            pa[2] = __float_as_uint(Ps[(wm + g) * PS_STRIDE + kb * 8 + tq + 4]);
            pa[3] = __float_as_uint(Ps[(wm + g + 8) * PS_STRIDE + kb * 8 + tq + 4]);
#pragma unroll
            for (int nt = 0; nt < 8; nt++) {
                unsigned b0 = __float_as_uint(bV[(kb * 8 + tq) * VS_STRIDE + nt * 8 + g]);
                unsigned b1 = __float_as_uint(bV[(kb * 8 + tq + 4) * VS_STRIDE + nt * 8 + g]);
                mma_tf32(o[nt], pa, b0, b1);
            }
        }
        __syncthreads();   // done reading cur before it is overwritten
    }

    const float inv_lo = 1.f / l_lo;
    const float inv_hi = 1.f / l_hi;
#pragma unroll
    for (int nt = 0; nt < 8; nt++) {
        const int c = h * HD + nt * 8 + 2 * tq;
        float2 v;  v.x  = f2tf(o[nt][0] * inv_lo); v.y  = f2tf(o[nt][1] * inv_lo);
        *(float2*)&Y[(size_t)(b * Tc + r_lo) * Cc + c] = v;
        float2 v2; v2.x = f2tf(o[nt][2] * inv_hi); v2.y = f2tf(o[nt][3] * inv_hi);
        *(float2*)&Y[(size_t)(b * Tc + r_hi) * Cc + c] = v2;
    }
}

// ---------------------------------------------------------------------------
// Launcher
// ---------------------------------------------------------------------------
extern "C" void kernel_launch(void* const* d_in, const int* in_sizes, int n_in,
                              void* d_out, int out_size)
{
    const float* x        = (const float*)d_in[0];
    const float* w_attn   = (const float*)d_in[1];
    const float* b_attn   = (const float*)d_in[2];
    const float* la_attn  = (const float*)d_in[3];
    const float* lb_attn  = (const float*)d_in[4];
    const float* w_proj   = (const float*)d_in[5];
    const float* b_proj   = (const float*)d_in[6];
    const float* la_proj  = (const float*)d_in[7];
    const float* lb_proj  = (const float*)d_in[8];
    float* out            = (float*)d_out;

    float *qkv, *y, *xa, *ya, *xc, *w1c, *w2c, *lb1c, *lb2c;
    cudaGetSymbolAddress((void**)&qkv,  g_qkv);
    cudaGetSymbolAddress((void**)&y,    g_y);
    cudaGetSymbolAddress((void**)&xa,   g_xa);
    cudaGetSymbolAddress((void**)&ya,   g_ya);
    cudaGetSymbolAddress((void**)&xc,   g_xc);
    cudaGetSymbolAddress((void**)&w1c,  g_w1c);
    cudaGetSymbolAddress((void**)&w2c,  g_w2c);
    cudaGetSymbolAddress((void**)&lb1c, g_lb1c);
    cudaGetSymbolAddress((void**)&lb2c, g_lb2c);

    cudaFuncSetAttribute(gemm_lora_tc<256, true>,
                         cudaFuncAttributeMaxDynamicSharedMemorySize, GEMM_SMEM(256));
    cudaFuncSetAttribute(gemm_lora_tc<128, false>,
                         cudaFuncAttributeMaxDynamicSharedMemorySize, GEMM_SMEM(128));
    cudaFuncSetAttribute(attn_tc,
                         cudaFuncAttributeMaxDynamicSharedMemorySize, ATTN_SMEM);

    // 0. tf32 pre-conversion
    prep_kernel<<<2048, 256>>>((const float4*)x, (const float4*)w_attn,
                               (const float4*)w_proj, (const float4*)lb_attn,
                               (const float4*)lb_proj,
                               (float4*)xc, (float4*)w1c, (float4*)w2c,
                               (float4*)lb1c, (float4*)lb2c);

    // 1. xa = x @ A_attn^T (tf32-rounded)
    lora_a_kernel<<<Mtot / 8, 256>>>(xc, la_attn, xa);

    // 2. qkv = [x|xa] @ [W|LB*s]^T + b (tf32-rounded output)
    {
        dim3 grid(N1 / 256, Mtot / 128);
        gemm_lora_tc<256, true><<<grid, 256, GEMM_SMEM(256)>>>(
            xc, w1c, b_attn, xa, lb1c, qkv, N1);
    }

    // 3. attention -> y (tf32-rounded)
    {
        dim3 grid(Tc / 64, Bc * NH);
        attn_tc<<<grid, 128, ATTN_SMEM>>>(qkv, y);
    }

    // 4. ya = y @ A_proj^T
    lora_a_kernel<<<Mtot / 8, 256>>>(y, la_proj, ya);

    // 5. out = [y|ya] @ [W|LB*s]^T + b (exact fp32 output)
    {
        dim3 grid(Cc / 128, Mtot / 128);
        gemm_lora_tc<128, false><<<grid, 256, GEMM_SMEM(128)>>>(
            y, w2c, b_proj, ya, lb2c, out, Cc);
    }
}

// round 4
// speedup vs baseline: 1.1203x; 1.1203x over previous
#include <cuda_runtime.h>
#include <math.h>
#include <stdint.h>

// Problem constants (fixed by setup_inputs)
#define Bc   2
#define Tc   2048
#define Cc   1024
#define NH   16
#define HD   64
#define Mtot (Bc * Tc)        // 4096
#define N1   (3 * Cc)         // 3072
#define Kc   Cc               // 1024
#define Rr   16
#define LORA_SCALE (1.0f / 16.0f)

// Scratch (device globals: allocation-free rule)
__device__ float g_qkv[Mtot * N1];    // 48 MB (tf32-rounded)
__device__ float g_y[Mtot * Cc];      // 16 MB (tf32-rounded)
__device__ float g_xa[Mtot * Rr];
__device__ float g_ya[Mtot * Rr];
__device__ float g_xc[Mtot * Kc];     // 16 MB x (tf32)
__device__ float g_w1c[N1 * Kc];      // 12 MB w_attn (tf32)
__device__ float g_w2c[Cc * Kc];      //  4 MB w_proj (tf32)
__device__ float g_lb1c[N1 * Rr];     // lora_b_attn * scale (tf32)
__device__ float g_lb2c[Cc * Rr];     // lora_b_proj * scale (tf32)

// ---------------------------------------------------------------------------
// helpers
// ---------------------------------------------------------------------------
__device__ __forceinline__ unsigned f2t(float f) {
    unsigned u;
    asm("cvt.rna.tf32.f32 %0, %1;" : "=r"(u) : "f"(f));
    return u;
}
__device__ __forceinline__ float f2tf(float f) { return __uint_as_float(f2t(f)); }

__device__ __forceinline__ void mma_tf32(float* d, const unsigned* a,
                                         unsigned b0, unsigned b1) {
    asm volatile(
        "mma.sync.aligned.m16n8k8.row.col.f32.tf32.tf32.f32 "
        "{%0,%1,%2,%3},{%4,%5,%6,%7},{%8,%9},{%0,%1,%2,%3};\n"
        : "+f"(d[0]), "+f"(d[1]), "+f"(d[2]), "+f"(d[3])
        : "r"(a[0]), "r"(a[1]), "r"(a[2]), "r"(a[3]), "r"(b0), "r"(b1));
}

__device__ __forceinline__ uint32_t smem_u32(const void* p) {
    return (uint32_t)__cvta_generic_to_shared(p);
}
__device__ __forceinline__ void cp16(uint32_t dst, const void* src) {
    asm volatile("cp.async.ca.shared.global [%0], [%1], 16;" :: "r"(dst), "l"(src));
}
__device__ __forceinline__ void cp_commit() {
    asm volatile("cp.async.commit_group;");
}
template <int N> __device__ __forceinline__ void cp_wait() {
    asm volatile("cp.async.wait_group %0;" :: "n"(N));
}

// ---------------------------------------------------------------------------
// prep: tf32-round x, w_attn, w_proj; tf32-round scaled lora_b's.
// ---------------------------------------------------------------------------
#define NX4   (Mtot * Kc / 4)
#define NW14  (N1 * Kc / 4)
#define NW24  (Cc * Kc / 4)
#define NL14  (N1 * Rr / 4)
#define NL24  (Cc * Rr / 4)
#define NTOT4 (NX4 + NW14 + NW24 + NL14 + NL24)

__global__ __launch_bounds__(256)
void prep_kernel(const float4* __restrict__ x,  const float4* __restrict__ w1,
                 const float4* __restrict__ w2, const float4* __restrict__ l1,
                 const float4* __restrict__ l2,
                 float4* __restrict__ xc,  float4* __restrict__ w1c,
                 float4* __restrict__ w2c, float4* __restrict__ l1c,
                 float4* __restrict__ l2c)
{
    for (int i = blockIdx.x * blockDim.x + threadIdx.x; i < NTOT4;
         i += gridDim.x * blockDim.x) {
        float4 v; float4* dst; float s = 1.f;
        if (i < NX4)                          { v = x[i];                          dst = xc  + i; }
        else if (i < NX4 + NW14)              { v = w1[i - NX4];                   dst = w1c + (i - NX4); }
        else if (i < NX4 + NW14 + NW24)       { v = w2[i - NX4 - NW14];            dst = w2c + (i - NX4 - NW14); }
        else if (i < NX4 + NW14 + NW24 + NL14){ v = l1[i - NX4 - NW14 - NW24];     dst = l1c + (i - NX4 - NW14 - NW24); s = LORA_SCALE; }
        else                                  { v = l2[i - NX4 - NW14 - NW24 - NL14]; dst = l2c + (i - NX4 - NW14 - NW24 - NL14); s = LORA_SCALE; }
        float4 o;
        o.x = f2tf(v.x * s); o.y = f2tf(v.y * s);
        o.z = f2tf(v.z * s); o.w = f2tf(v.w * s);
        *dst = o;
    }
}

// ---------------------------------------------------------------------------
// LoRA A projection: XA[m,r] = sum_k X[m,k] * A[r,k]; writes tf32-rounded.
// ---------------------------------------------------------------------------
__global__ __launch_bounds__(256)
void lora_a_kernel(const float* __restrict__ X,
                   const float* __restrict__ Aw,
                   float* __restrict__ XA)
{
    const int lane = threadIdx.x & 31;
    const int w    = threadIdx.x >> 5;
    const int m    = blockIdx.x * 8 + w;

    float acc[Rr];
#pragma unroll
    for (int r = 0; r < Rr; r++) acc[r] = 0.f;

    const float* xr = X + (size_t)m * Kc;
#pragma unroll
    for (int it = 0; it < 8; it++) {
        int k = (it * 32 + lane) * 4;
        float4 xv = *(const float4*)&xr[k];
#pragma unroll
        for (int r = 0; r < Rr; r++) {
            float4 av = *(const float4*)&Aw[r * Kc + k];
            acc[r] += xv.x * av.x + xv.y * av.y + xv.z * av.z + xv.w * av.w;
        }
    }
#pragma unroll
    for (int r = 0; r < Rr; r++) {
        float v = acc[r];
#pragma unroll
        for (int off = 16; off; off >>= 1) v += __shfl_xor_sync(0xffffffffu, v, off);
        acc[r] = f2tf(v);
    }
    if (lane == 0) {
        float4* dst = (float4*)&XA[(size_t)m * Rr];
        dst[0] = make_float4(acc[0],  acc[1],  acc[2],  acc[3]);
        dst[1] = make_float4(acc[4],  acc[5],  acc[6],  acc[7]);
        dst[2] = make_float4(acc[8],  acc[9],  acc[10], acc[11]);
        dst[3] = make_float4(acc[12], acc[13], acc[14], acc[15]);
    }
}

// ---------------------------------------------------------------------------
// tf32 GEMM, cp.async double-buffered, LoRA folded as final K-stage:
//   out = [A | XA] @ [W | LBs]^T + bias
// Block 128x128, BK=32, 256 threads, 8 warps (2x4), warp tile 64x32.
// __launch_bounds__(256,2): ~120 regs -> 2 blocks/SM = 16 warps.
// ---------------------------------------------------------------------------
#define GBK 32
#define GSTR 36
#define GBN 128
#define GNT 4

template <bool ROUND>
__global__ __launch_bounds__(256, 2)
void gemm_lora_tc(const float* __restrict__ A, const float* __restrict__ W,
                  const float* __restrict__ bias, const float* __restrict__ XA,
                  const float* __restrict__ LBs, float* __restrict__ out, int N)
{
    extern __shared__ float sm[];
    float* sA = sm;                             // [2][128][GSTR]
    float* sW = sm + 2 * 128 * GSTR;            // [2][128][GSTR]

    const int tid  = threadIdx.x;
    const int row0 = blockIdx.y * 128;
    const int col0 = blockIdx.x * GBN;
    const int lane = tid & 31, wid = tid >> 5;
    const int wm = (wid >> 2) * 64;
    const int wn = (wid & 3) * 32;
    const int g  = lane >> 2, tq = lane & 3;

    const int arow = tid >> 1;
    const int akb  = (tid & 1) * 16;

    float acc[4][GNT][4];
#pragma unroll
    for (int mt = 0; mt < 4; mt++)
#pragma unroll
        for (int nt = 0; nt < GNT; nt++)
#pragma unroll
            for (int i = 0; i < 4; i++) acc[mt][nt][i] = 0.f;

    const int NMAIN = Kc / GBK;     // 32
    const int NST   = NMAIN + 1;    // + LoRA stage

    auto load_main = [&](int s, int buf) {
        const float* pa = A + (size_t)(row0 + arow) * Kc + s * GBK + akb;
        uint32_t da = smem_u32(&sA[(buf * 128 + arow) * GSTR + akb]);
        cp16(da,      pa);     cp16(da + 16, pa + 4);
        cp16(da + 32, pa + 8); cp16(da + 48, pa + 12);
        const float* pw = W + (size_t)(col0 + arow) * Kc + s * GBK + akb;
        uint32_t dw = smem_u32(&sW[(buf * 128 + arow) * GSTR + akb]);
        cp16(dw,      pw);     cp16(dw + 16, pw + 4);
        cp16(dw + 32, pw + 8); cp16(dw + 48, pw + 12);
    };
    auto load_lora = [&](int buf) {
        const int kb2 = (tid & 1) * 8;
        const float* pa = XA + (size_t)(row0 + arow) * Rr + kb2;
        uint32_t da = smem_u32(&sA[(buf * 128 + arow) * GSTR + kb2]);
        cp16(da, pa); cp16(da + 16, pa + 4);
        const float* pw = LBs + (size_t)(col0 + arow) * Rr + kb2;
        uint32_t dw = smem_u32(&sW[(buf * 128 + arow) * GSTR + kb2]);
        cp16(dw, pw); cp16(dw + 16, pw + 4);
    };
    auto compute = [&](int buf, int nk8) {
        const float* bA = sA + (size_t)buf * 128 * GSTR;
        const float* bW = sW + (size_t)buf * 128 * GSTR;
        for (int k8 = 0; k8 < nk8; k8++) {
            const int k = k8 * 8;
            unsigned af[4][4], bf[GNT][2];
#pragma unroll
            for (int mt = 0; mt < 4; mt++) {
                const int r0 = wm + mt * 16;
                af[mt][0] = __float_as_uint(bA[(r0 + g) * GSTR + k + tq]);
                af[mt][1] = __float_as_uint(bA[(r0 + g + 8) * GSTR + k + tq]);
                af[mt][2] = __float_as_uint(bA[(r0 + g) * GSTR + k + tq + 4]);
                af[mt][3] = __float_as_uint(bA[(r0 + g + 8) * GSTR + k + tq + 4]);
            }
#pragma unroll
            for (int nt = 0; nt < GNT; nt++) {
                const int c0 = wn + nt * 8;
                bf[nt][0] = __float_as_uint(bW[(c0 + g) * GSTR + k + tq]);
                bf[nt][1] = __float_as_uint(bW[(c0 + g) * GSTR + k + tq + 4]);
            }
#pragma unroll
            for (int mt = 0; mt < 4; mt++)
#pragma unroll
                for (int nt = 0; nt < GNT; nt++)
                    mma_tf32(acc[mt][nt], af[mt], bf[nt][0], bf[nt][1]);
        }
    };

    load_main(0, 0);
    cp_commit();

    for (int s = 0; s < NST; s++) {
        const int cur = s & 1;
        const bool hn = (s + 1 < NST);
        if (hn) {
            if (s + 1 < NMAIN) load_main(s + 1, cur ^ 1);
            else               load_lora(cur ^ 1);
            cp_commit();
            cp_wait<1>();
        } else {
            cp_wait<0>();
        }
        __syncthreads();
        compute(cur, (s < NMAIN) ? 4 : 2);
        __syncthreads();
    }

#pragma unroll
    for (int nt = 0; nt < GNT; nt++) {
        const int c = col0 + wn + nt * 8 + 2 * tq;
        const float b0 = bias[c], b1 = bias[c + 1];
#pragma unroll
        for (int mt = 0; mt < 4; mt++) {
            const int r = row0 + wm + mt * 16 + g;
            float2 lo, hi;
            if (ROUND) {
                lo.x = f2tf(acc[mt][nt][0] + b0); lo.y = f2tf(acc[mt][nt][1] + b1);
                hi.x = f2tf(acc[mt][nt][2] + b0); hi.y = f2tf(acc[mt][nt][3] + b1);
            } else {
                lo.x = acc[mt][nt][0] + b0; lo.y = acc[mt][nt][1] + b1;
                hi.x = acc[mt][nt][2] + b0; hi.y = acc[mt][nt][3] + b1;
            }
            *(float2*)&out[(size_t)r * N + c] = lo;
            *(float2*)&out[(size_t)(r + 8) * N + c] = hi;
        }
    }
}

#define GEMM_SMEM ((2 * 128 * GSTR + 2 * 128 * GSTR) * 4)

// ---------------------------------------------------------------------------
// Flash attention, tf32 mma. No P smem: S C-fragments are transposed into PV
// A-fragments via quad shuffles. K double-buffered, V single-buffered
// (cp.async). 53KB smem + <=128 regs -> 4 blocks/SM = 16 warps.
// Heavy-first block order (big qb launches first).
// ---------------------------------------------------------------------------
#define KS_STRIDE 68
#define VS_STRIDE 72
#define ATTN_SMEM ((2 * 64 * KS_STRIDE + 64 * VS_STRIDE) * 4)

__global__ __launch_bounds__(128, 4)
void attn_tc(const float* __restrict__ qkv, float* __restrict__ Y)
{
    extern __shared__ float sm[];
    float* Ks = sm;                          // [2][64][KS_STRIDE]
    float* Vs = sm + 2 * 64 * KS_STRIDE;     // [64][VS_STRIDE]

    const int bid = blockIdx.x;
    const int qb  = (Tc / 64 - 1) - (bid >> 5);  // heavy blocks first
    const int bh  = bid & 31;
    const int b   = bh >> 4;
    const int h   = bh & 15;
    const int tid = threadIdx.x;
    const int lane = tid & 31, wid = tid >> 5;
    const int wm  = wid * 16;
    const int g   = lane >> 2, tq = lane & 3;
    const int qg0 = qb * 64;

    const float* qptr = qkv + (size_t)(b * Tc) * N1 + h * HD;
    const float* kptr = qptr + Cc;
    const float* vptr = qptr + 2 * Cc;

    const int krow  = tid >> 1;
    const int kcol0 = (tid & 1) * 32;

    auto load_k = [&](int jt, int buf) {
        const float* pk = kptr + (size_t)(jt * 64 + krow) * N1 + kcol0;
        uint32_t dk = smem_u32(&Ks[(buf * 64 + krow) * KS_STRIDE + kcol0]);
#pragma unroll
        for (int c = 0; c < 8; c++) cp16(dk + 16 * c, pk + 4 * c);
    };
    auto load_v = [&](int jt) {
        const float* pv = vptr + (size_t)(jt * 64 + krow) * N1 + kcol0;
        uint32_t dv = smem_u32(&Vs[krow * VS_STRIDE + kcol0]);
#pragma unroll
        for (int c = 0; c < 8; c++) cp16(dv + 16 * c, pv + 4 * c);
    };

    load_k(0, 0);
    cp_commit();

    // Q fragments straight from gmem (values already tf32; *0.125 exact)
    unsigned qa[8][4];
    {
        const float* q0 = qptr + (size_t)(qg0 + wm + g) * N1;
        const float* q1 = q0 + 8 * (size_t)N1;
#pragma unroll
        for (int kb = 0; kb < 8; kb++) {
            qa[kb][0] = __float_as_uint(q0[kb * 8 + tq]     * 0.125f);
            qa[kb][1] = __float_as_uint(q1[kb * 8 + tq]     * 0.125f);
            qa[kb][2] = __float_as_uint(q0[kb * 8 + tq + 4] * 0.125f);
            qa[kb][3] = __float_as_uint(q1[kb * 8 + tq + 4] * 0.125f);
        }
    }

    float o[8][4];
#pragma unroll
    for (int nt = 0; nt < 8; nt++)
#pragma unroll
        for (int i = 0; i < 4; i++) o[nt][i] = 0.f;
    float m_lo = -INFINITY, m_hi = -INFINITY, l_lo = 0.f, l_hi = 0.f;

    const int r_lo = qg0 + wm + g;
    const int r_hi = r_lo + 8;
    const int srcA = (lane & ~3) | (tq >> 1);   // quad-shuffle sources for P^T
    const int srcB = srcA + 2;
    const bool odd = (tq & 1);

    for (int jt = 0; jt <= qb; jt++) {
        const int cur = jt & 1;
        const bool hn = jt < qb;
        load_v(jt); cp_commit();
        if (hn) { load_k(jt + 1, cur ^ 1); cp_commit(); cp_wait<2>(); }
        else    { cp_wait<1>(); }
        __syncthreads();   // K(jt) visible; prev-iter V readers done

        const float* bK = Ks + (size_t)cur * 64 * KS_STRIDE;

        // S = Q @ K^T
        float sc[8][4];
#pragma unroll
        for (int nt = 0; nt < 8; nt++) {
#pragma unroll
            for (int i = 0; i < 4; i++) sc[nt][i] = 0.f;
#pragma unroll
            for (int kb = 0; kb < 8; kb++) {
                unsigned b0 = __float_as_uint(bK[(nt * 8 + g) * KS_STRIDE + kb * 8 + tq]);
                unsigned b1 = __float_as_uint(bK[(nt * 8 + g) * KS_STRIDE + kb * 8 + tq + 4]);
                mma_tf32(sc[nt], qa[kb], b0, b1);
            }
        }

        // causal mask on the diagonal tile
        if (jt == qb) {
#pragma unroll
            for (int nt = 0; nt < 8; nt++) {
                const int c = qg0 + nt * 8 + 2 * tq;
                if (c     > r_lo) sc[nt][0] = -INFINITY;
                if (c + 1 > r_lo) sc[nt][1] = -INFINITY;
                if (c     > r_hi) sc[nt][2] = -INFINITY;
                if (c + 1 > r_hi) sc[nt][3] = -INFINITY;
            }
        }

        // online softmax
        float tmax_lo = -INFINITY, tmax_hi = -INFINITY;
#pragma unroll
        for (int nt = 0; nt < 8; nt++) {
            tmax_lo = fmaxf(tmax_lo, fmaxf(sc[nt][0], sc[nt][1]));
            tmax_hi = fmaxf(tmax_hi, fmaxf(sc[nt][2], sc[nt][3]));
        }
        tmax_lo = fmaxf(tmax_lo, __shfl_xor_sync(0xffffffffu, tmax_lo, 1));
        tmax_lo = fmaxf(tmax_lo, __shfl_xor_sync(0xffffffffu, tmax_lo, 2));
        tmax_hi = fmaxf(tmax_hi, __shfl_xor_sync(0xffffffffu, tmax_hi, 1));
        tmax_hi = fmaxf(tmax_hi, __shfl_xor_sync(0xffffffffu, tmax_hi, 2));

        const float mn_lo = fmaxf(m_lo, tmax_lo);
        const float mn_hi = fmaxf(m_hi, tmax_hi);
        const float corr_lo = __expf(m_lo - mn_lo);
        const float corr_hi = __expf(m_hi - mn_hi);
        m_lo = mn_lo; m_hi = mn_hi;

        float ls_lo = 0.f, ls_hi = 0.f;
#pragma unroll
        for (int nt = 0; nt < 8; nt++) {
            float p0 = __expf(sc[nt][0] - mn_lo);
            float p1 = __expf(sc[nt][1] - mn_lo);
            float p2 = __expf(sc[nt][2] - mn_hi);
            float p3 = __expf(sc[nt][3] - mn_hi);
            ls_lo += p0 + p1;
            ls_hi += p2 + p3;
            sc[nt][0] = f2tf(p0); sc[nt][1] = f2tf(p1);
            sc[nt][2] = f2tf(p2); sc[nt][3] = f2tf(p3);
        }
        ls_lo += __shfl_xor_sync(0xffffffffu, ls_lo, 1);
        ls_lo += __shfl_xor_sync(0xffffffffu, ls_lo, 2);
        ls_hi += __shfl_xor_sync(0xffffffffu, ls_hi, 1);
        ls_hi += __shfl_xor_sync(0xffffffffu, ls_hi, 2);
        l_lo = l_lo * corr_lo + ls_lo;
        l_hi = l_hi * corr_hi + ls_hi;

#pragma unroll
        for (int nt = 0; nt < 8; nt++) {
            o[nt][0] *= corr_lo; o[nt][1] *= corr_lo;
            o[nt][2] *= corr_hi; o[nt][3] *= corr_hi;
        }

        if (hn) cp_wait<1>(); else cp_wait<0>();
        __syncthreads();   // V(jt) visible

        // O += P @ V; A-fragments of P built from S C-fragments via shuffles:
        // lane(g,tq) needs P[g][8kb+tq] = element (tq&1) of lane (g, tq>>1).
#pragma unroll
        for (int kb = 0; kb < 8; kb++) {
            float e0A = __shfl_sync(0xffffffffu, sc[kb][0], srcA);
            float e1A = __shfl_sync(0xffffffffu, sc[kb][1], srcA);
            float e2A = __shfl_sync(0xffffffffu, sc[kb][2], srcA);
            float e3A = __shfl_sync(0xffffffffu, sc[kb][3], srcA);
            float e0B = __shfl_sync(0xffffffffu, sc[kb][0], srcB);
            float e1B = __shfl_sync(0xffffffffu, sc[kb][1], srcB);
            float e2B = __shfl_sync(0xffffffffu, sc[kb][2], srcB);
            float e3B = __shfl_sync(0xffffffffu, sc[kb][3], srcB);
            unsigned pa[4];
            pa[0] = __float_as_uint(odd ? e1A : e0A);
            pa[1] = __float_as_uint(odd ? e3A : e2A);
            pa[2] = __float_as_uint(odd ? e1B : e0B);
            pa[3] = __float_as_uint(odd ? e3B : e2B);
#pragma unroll
            for (int nt = 0; nt < 8; nt++) {
                unsigned b0 = __float_as_uint(Vs[(kb * 8 + tq) * VS_STRIDE + nt * 8 + g]);
                unsigned b1 = __float_as_uint(Vs[(kb * 8 + tq + 4) * VS_STRIDE + nt * 8 + g]);
                mma_tf32(o[nt], pa, b0, b1);
            }
        }
        __syncthreads();   // V readers done before next iter's load_v
    }

    const float inv_lo = 1.f / l_lo;
    const float inv_hi = 1.f / l_hi;
#pragma unroll
    for (int nt = 0; nt < 8; nt++) {
        const int c = h * HD + nt * 8 + 2 * tq;
        float2 v;  v.x  = f2tf(o[nt][0] * inv_lo); v.y  = f2tf(o[nt][1] * inv_lo);
        *(float2*)&Y[(size_t)(b * Tc + r_lo) * Cc + c] = v;
        float2 v2; v2.x = f2tf(o[nt][2] * inv_hi); v2.y = f2tf(o[nt][3] * inv_hi);
        *(float2*)&Y[(size_t)(b * Tc + r_hi) * Cc + c] = v2;
    }
}

// ---------------------------------------------------------------------------
// Launcher
// ---------------------------------------------------------------------------
extern "C" void kernel_launch(void* const* d_in, const int* in_sizes, int n_in,
                              void* d_out, int out_size)
{
    const float* x        = (const float*)d_in[0];
    const float* w_attn   = (const float*)d_in[1];
    const float* b_attn   = (const float*)d_in[2];
    const float* la_attn  = (const float*)d_in[3];
    const float* lb_attn  = (const float*)d_in[4];
    const float* w_proj   = (const float*)d_in[5];
    const float* b_proj   = (const float*)d_in[6];
    const float* la_proj  = (const float*)d_in[7];
    const float* lb_proj  = (const float*)d_in[8];
    float* out            = (float*)d_out;

    float *qkv, *y, *xa, *ya, *xc, *w1c, *w2c, *lb1c, *lb2c;
    cudaGetSymbolAddress((void**)&qkv,  g_qkv);
    cudaGetSymbolAddress((void**)&y,    g_y);
    cudaGetSymbolAddress((void**)&xa,   g_xa);
    cudaGetSymbolAddress((void**)&ya,   g_ya);
    cudaGetSymbolAddress((void**)&xc,   g_xc);
    cudaGetSymbolAddress((void**)&w1c,  g_w1c);
    cudaGetSymbolAddress((void**)&w2c,  g_w2c);
    cudaGetSymbolAddress((void**)&lb1c, g_lb1c);
    cudaGetSymbolAddress((void**)&lb2c, g_lb2c);

    cudaFuncSetAttribute(gemm_lora_tc<true>,
                         cudaFuncAttributeMaxDynamicSharedMemorySize, GEMM_SMEM);
    cudaFuncSetAttribute(gemm_lora_tc<false>,
                         cudaFuncAttributeMaxDynamicSharedMemorySize, GEMM_SMEM);
    cudaFuncSetAttribute(attn_tc,
                         cudaFuncAttributeMaxDynamicSharedMemorySize, ATTN_SMEM);

    // 0. tf32 pre-conversion
    prep_kernel<<<2048, 256>>>((const float4*)x, (const float4*)w_attn,
                               (const float4*)w_proj, (const float4*)lb_attn,
                               (const float4*)lb_proj,
                               (float4*)xc, (float4*)w1c, (float4*)w2c,
                               (float4*)lb1c, (float4*)lb2c);

    // 1. xa = x @ A_attn^T (tf32-rounded)
    lora_a_kernel<<<Mtot / 8, 256>>>(xc, la_attn, xa);

    // 2. qkv = [x|xa] @ [W|LB*s]^T + b (tf32-rounded output)
    {
        dim3 grid(N1 / GBN, Mtot / 128);
        gemm_lora_tc<true><<<grid, 256, GEMM_SMEM>>>(
            xc, w1c, b_attn, xa, lb1c, qkv, N1);
    }

    // 3. attention -> y (tf32-rounded)
    attn_tc<<<(Tc / 64) * Bc * NH, 128, ATTN_SMEM>>>(qkv, y);

    // 4. ya = y @ A_proj^T
    lora_a_kernel<<<Mtot / 8, 256>>>(y, la_proj, ya);

    // 5. out = [y|ya] @ [W|LB*s]^T + b (exact fp32 output)
    {
        dim3 grid(Cc / GBN, Mtot / 128);
        gemm_lora_tc<false><<<grid, 256, GEMM_SMEM>>>(
            y, w2c, b_proj, ya, lb2c, out, Cc);
    }
}

// round 5
// speedup vs baseline: 1.1418x; 1.0192x over previous
#include <cuda_runtime.h>
#include <math.h>
#include <stdint.h>

// Problem constants (fixed by setup_inputs)
#define Bc   2
#define Tc   2048
#define Cc   1024
#define NH   16
#define HD   64
#define Mtot (Bc * Tc)        // 4096
#define N1   (3 * Cc)         // 3072
#define Kc   Cc               // 1024
#define Rr   16
#define LORA_SCALE (1.0f / 16.0f)

// Scratch (device globals: allocation-free rule)
__device__ float g_qkv[Mtot * N1];    // q,k parts used (P4' cols, tf32)
__device__ float g_v[Mtot * Cc];      // v in [b,h,d,t_perm] layout (tf32)
__device__ float g_y[Mtot * Cc];      // attention out (P4' cols, tf32)
__device__ float g_xa[Mtot * Rr];     // P4' cols
__device__ float g_ya[Mtot * Rr];     // P4' cols
__device__ float g_xc[Mtot * Kc];     // x   (P4' cols, tf32)
__device__ float g_w1c[N1 * Kc];      // w_attn (P4' cols, tf32)
__device__ float g_w2c[Cc * Kc];      // w_proj (P4' cols, tf32)
__device__ float g_lb1c[N1 * Rr];     // lora_b_attn * scale (P4', tf32)
__device__ float g_lb2c[Cc * Rr];     // lora_b_proj * scale (P4', tf32)
__device__ float g_la2c[Rr * Kc];     // lora_a_proj (P4', fp32)

// ---------------------------------------------------------------------------
// helpers
// ---------------------------------------------------------------------------
__device__ __forceinline__ unsigned f2t(float f) {
    unsigned u;
    asm("cvt.rna.tf32.f32 %0, %1;" : "=r"(u) : "f"(f));
    return u;
}
__device__ __forceinline__ float f2tf(float f) { return __uint_as_float(f2t(f)); }

__device__ __forceinline__ void mma_tf32(float* d, const unsigned* a,
                                         unsigned b0, unsigned b1) {
    asm volatile(
        "mma.sync.aligned.m16n8k8.row.col.f32.tf32.tf32.f32 "
        "{%0,%1,%2,%3},{%4,%5,%6,%7},{%8,%9},{%0,%1,%2,%3};\n"
        : "+f"(d[0]), "+f"(d[1]), "+f"(d[2]), "+f"(d[3])
        : "r"(a[0]), "r"(a[1]), "r"(a[2]), "r"(a[3]), "r"(b0), "r"(b1));
}

__device__ __forceinline__ uint32_t smem_u32(const void* p) {
    return (uint32_t)__cvta_generic_to_shared(p);
}
__device__ __forceinline__ void cp16(uint32_t dst, const void* src) {
    asm volatile("cp.async.ca.shared.global [%0], [%1], 16;" :: "r"(dst), "l"(src));
}
__device__ __forceinline__ void cp_commit() {
    asm volatile("cp.async.commit_group;");
}
template <int N> __device__ __forceinline__ void cp_wait() {
    asm volatile("cp.async.wait_group %0;" :: "n"(N));
}

// P4' permuted scatter-store of 4 consecutive (flat) floats.
// P4' within 8-group: j -> (j&3)*2 + (j>>2). flat%8 is 0 or 4.
__device__ __forceinline__ void store_perm4(float* dst, int flat, float4 o) {
    int base = flat & ~7;
    int off  = (flat & 4) ? 1 : 0;
    dst[base + off + 0] = o.x;
    dst[base + off + 2] = o.y;
    dst[base + off + 4] = o.z;
    dst[base + off + 6] = o.w;
}

// ---------------------------------------------------------------------------
// prep: tf32-round + P4'-permute x, w_attn, w_proj, scaled lora_b's;
// P4'-permute lora_a_proj (full fp32).
// ---------------------------------------------------------------------------
#define NX4   (Mtot * Kc / 4)
#define NW14  (N1 * Kc / 4)
#define NW24  (Cc * Kc / 4)
#define NL14  (N1 * Rr / 4)
#define NL24  (Cc * Rr / 4)
#define NA24  (Rr * Kc / 4)
#define NTOT4 (NX4 + NW14 + NW24 + NL14 + NL24 + NA24)

__global__ __launch_bounds__(256)
void prep_kernel(const float4* __restrict__ x,  const float4* __restrict__ w1,
                 const float4* __restrict__ w2, const float4* __restrict__ l1,
                 const float4* __restrict__ l2, const float4* __restrict__ la2,
                 float* __restrict__ xc,  float* __restrict__ w1c,
                 float* __restrict__ w2c, float* __restrict__ l1c,
                 float* __restrict__ l2c, float* __restrict__ la2c)
{
    for (int i = blockIdx.x * blockDim.x + threadIdx.x; i < NTOT4;
         i += gridDim.x * blockDim.x) {
        float4 v; float* dst; int loc; float s = 1.f; bool rnd = true;
        int j = i;
        if (j < NX4)                { v = x[j];  dst = xc;  loc = j; }
        else if ((j -= NX4) < NW14) { v = w1[j]; dst = w1c; loc = j; }
        else if ((j -= NW14) < NW24){ v = w2[j]; dst = w2c; loc = j; }
        else if ((j -= NW24) < NL14){ v = l1[j]; dst = l1c; loc = j; s = LORA_SCALE; }
        else if ((j -= NL14) < NL24){ v = l2[j]; dst = l2c; loc = j; s = LORA_SCALE; }
        else { j -= NL24;            v = la2[j]; dst = la2c; loc = j; rnd = false; }
        float4 o;
        if (rnd) {
            o.x = f2tf(v.x * s); o.y = f2tf(v.y * s);
            o.z = f2tf(v.z * s); o.w = f2tf(v.w * s);
        } else o = v;
        store_perm4(dst, loc * 4, o);
    }
}

// ---------------------------------------------------------------------------
// LoRA A projection: XA[m,r] = sum_k X[m,k] * A[r,k]; fp32 dot, tf32-rounded,
// written P4'-permuted over the 16 r-columns. X and A must share the same
// column permutation (raw+raw, or perm+perm).
// ---------------------------------------------------------------------------
__global__ __launch_bounds__(256)
void lora_a_kernel(const float* __restrict__ X,
                   const float* __restrict__ Aw,
                   float* __restrict__ XA)
{
    const int lane = threadIdx.x & 31;
    const int w    = threadIdx.x >> 5;
    const int m    = blockIdx.x * 8 + w;

    float acc[Rr];
#pragma unroll
    for (int r = 0; r < Rr; r++) acc[r] = 0.f;

    const float* xr = X + (size_t)m * Kc;
#pragma unroll
    for (int it = 0; it < 8; it++) {
        int k = (it * 32 + lane) * 4;
        float4 xv = *(const float4*)&xr[k];
#pragma unroll
        for (int r = 0; r < Rr; r++) {
            float4 av = *(const float4*)&Aw[r * Kc + k];
            acc[r] += xv.x * av.x + xv.y * av.y + xv.z * av.z + xv.w * av.w;
        }
    }
#pragma unroll
    for (int r = 0; r < Rr; r++) {
        float v = acc[r];
#pragma unroll
        for (int off = 16; off; off >>= 1) v += __shfl_xor_sync(0xffffffffu, v, off);
        acc[r] = f2tf(v);
    }
    if (lane == 0) {
        float4* dst = (float4*)&XA[(size_t)m * Rr];
        // P4' packing: pos p holds r = (p&1)*4 + (p>>1)
        dst[0] = make_float4(acc[0],  acc[4],  acc[1],  acc[5]);
        dst[1] = make_float4(acc[2],  acc[6],  acc[3],  acc[7]);
        dst[2] = make_float4(acc[8],  acc[12], acc[9],  acc[13]);
        dst[3] = make_float4(acc[10], acc[14], acc[11], acc[15]);
    }
}

// ---------------------------------------------------------------------------
// tf32 GEMM, cp.async double-buffered, LoRA folded as final K-stage.
// All K-dim inputs P4'-permuted -> fragment pairs via LDS.64 (GSTR=40,
// conflict-free). MODE 0: qkv output (q/k parts P4'-permuted + tf32-rounded;
// v part transposed into gv[b,h,d,t_perm]). MODE 1: plain fp32 output.
// ---------------------------------------------------------------------------
#define GBK 32
#define GSTR 40
#define GBN 128

template <int MODE>
__global__ __launch_bounds__(256, 2)
void gemm_lora_tc(const float* __restrict__ A, const float* __restrict__ W,
                  const float* __restrict__ bias, const float* __restrict__ XA,
                  const float* __restrict__ LBs, float* __restrict__ out,
                  float* __restrict__ gv, int N)
{
    extern __shared__ float sm[];
    float* sA = sm;                             // [2][128][GSTR]
    float* sW = sm + 2 * 128 * GSTR;            // [2][128][GSTR]

    const int tid  = threadIdx.x;
    const int row0 = blockIdx.y * 128;
    const int col0 = blockIdx.x * GBN;
    const int lane = tid & 31, wid = tid >> 5;
    const int wm = (wid >> 2) * 64;
    const int wn = (wid & 3) * 32;
    const int g  = lane >> 2, tq = lane & 3;

    const int arow = tid >> 1;
    const int akb  = (tid & 1) * 16;

    float acc[4][4][4];
#pragma unroll
    for (int mt = 0; mt < 4; mt++)
#pragma unroll
        for (int nt = 0; nt < 4; nt++)
#pragma unroll
            for (int i = 0; i < 4; i++) acc[mt][nt][i] = 0.f;

    const int NMAIN = Kc / GBK;     // 32
    const int NST   = NMAIN + 1;    // + LoRA stage

    auto load_main = [&](int s, int buf) {
        const float* pa = A + (size_t)(row0 + arow) * Kc + s * GBK + akb;
        uint32_t da = smem_u32(&sA[(buf * 128 + arow) * GSTR + akb]);
        cp16(da,      pa);     cp16(da + 16, pa + 4);
        cp16(da + 32, pa + 8); cp16(da + 48, pa + 12);
        const float* pw = W + (size_t)(col0 + arow) * Kc + s * GBK + akb;
        uint32_t dw = smem_u32(&sW[(buf * 128 + arow) * GSTR + akb]);
        cp16(dw,      pw);     cp16(dw + 16, pw + 4);
        cp16(dw + 32, pw + 8); cp16(dw + 48, pw + 12);
    };
    auto load_lora = [&](int buf) {
        const int kb2 = (tid & 1) * 8;
        const float* pa = XA + (size_t)(row0 + arow) * Rr + kb2;
        uint32_t da = smem_u32(&sA[(buf * 128 + arow) * GSTR + kb2]);
        cp16(da, pa); cp16(da + 16, pa + 4);
        const float* pw = LBs + (size_t)(col0 + arow) * Rr + kb2;
        uint32_t dw = smem_u32(&sW[(buf * 128 + arow) * GSTR + kb2]);
        cp16(dw, pw); cp16(dw + 16, pw + 4);
    };
    auto compute = [&](int buf, int nk8) {
        const float* bA = sA + (size_t)buf * 128 * GSTR;
        const float* bW = sW + (size_t)buf * 128 * GSTR;
        for (int k8 = 0; k8 < nk8; k8++) {
            const int kp = k8 * 8 + tq * 2;     // P4' fragment pair position
            unsigned af[4][4], bf[4][2];
#pragma unroll
            for (int mt = 0; mt < 4; mt++) {
                const int r0 = wm + mt * 16;
                float2 fa0 = *(const float2*)&bA[(r0 + g) * GSTR + kp];
                float2 fa1 = *(const float2*)&bA[(r0 + g + 8) * GSTR + kp];
                af[mt][0] = __float_as_uint(fa0.x);
                af[mt][1] = __float_as_uint(fa1.x);
                af[mt][2] = __float_as_uint(fa0.y);
                af[mt][3] = __float_as_uint(fa1.y);
            }
#pragma unroll
            for (int nt = 0; nt < 4; nt++) {
                float2 fb = *(const float2*)&bW[(wn + nt * 8 + g) * GSTR + kp];
                bf[nt][0] = __float_as_uint(fb.x);
                bf[nt][1] = __float_as_uint(fb.y);
            }
#pragma unroll
            for (int mt = 0; mt < 4; mt++)
#pragma unroll
                for (int nt = 0; nt < 4; nt++)
                    mma_tf32(acc[mt][nt], af[mt], bf[nt][0], bf[nt][1]);
        }
    };

    load_main(0, 0);
    cp_commit();

    for (int s = 0; s < NST; s++) {
        const int cur = s & 1;
        const bool hn = (s + 1 < NST);
        if (hn) {
            if (s + 1 < NMAIN) load_main(s + 1, cur ^ 1);
            else               load_lora(cur ^ 1);
            cp_commit();
            cp_wait<1>();
        } else {
            cp_wait<0>();
        }
        __syncthreads();
        compute(cur, (s < NMAIN) ? 4 : 2);
        __syncthreads();
    }

    // epilogue
    const bool isv = (MODE == 0) && (col0 >= 2 * Cc);
#pragma unroll
    for (int nt = 0; nt < 4; nt++) {
        const int n = col0 + wn + nt * 8 + 2 * tq;   // even
        const float b0 = bias[n], b1 = bias[n + 1];
#pragma unroll
        for (int mt = 0; mt < 4; mt++) {
            const int r = row0 + wm + mt * 16 + g;
            if (MODE == 1) {
                float2 lo; lo.x = acc[mt][nt][0] + b0; lo.y = acc[mt][nt][1] + b1;
                *(float2*)&out[(size_t)r * N + n] = lo;
                float2 hi; hi.x = acc[mt][nt][2] + b0; hi.y = acc[mt][nt][3] + b1;
                *(float2*)&out[(size_t)(r + 8) * N + n] = hi;
            } else {
                float v0 = f2tf(acc[mt][nt][0] + b0);
                float v1 = f2tf(acc[mt][nt][1] + b1);
                float v2 = f2tf(acc[mt][nt][2] + b0);
                float v3 = f2tf(acc[mt][nt][3] + b1);
                if (!isv) {
                    // P4' on output cols
                    const int base = n & ~7;
                    const int p = ((n & 3) << 1) + ((n >> 2) & 1);
                    float* o0 = &out[(size_t)r * N + base];
                    float* o1 = &out[(size_t)(r + 8) * N + base];
                    o0[p] = v0; o0[p + 2] = v1;
                    o1[p] = v2; o1[p + 2] = v3;
                } else {
                    // transposed v: gv[b, h, d, t_perm]
                    const int dg = n - 2 * Cc;
                    const int h  = dg >> 6, dd = dg & 63;
                    const int bb = r >> 11, t = r & (Tc - 1);
                    const int tp = (t & ~7) + ((t & 3) << 1) + ((t >> 2) & 1);
                    float* vb = &gv[(((size_t)(bb * NH + h)) * HD + dd) * Tc + tp];
                    vb[0]      = v0;  vb[Tc]     = v1;   // (dd, t), (dd+1, t)
                    vb[8]      = v2;  vb[Tc + 8] = v3;   // t+8 rows
                }
            }
        }
    }
}

#define GEMM_SMEM ((2 * 128 * GSTR + 2 * 128 * GSTR) * 4)

// ---------------------------------------------------------------------------
// Flash attention, tf32 mma. K rows P4' on d; V stored [d][t_perm] (gv) so
// both S and PV B-fragment pairs are single conflict-free LDS.64 reads.
// K double-buffered, Vt single-buffered (cp.async). 54KB smem, 4 blocks/SM.
// ---------------------------------------------------------------------------
#define KS_STRIDE 72
#define VS_STRIDE 72
#define ATTN_SMEM ((2 * 64 * KS_STRIDE + 64 * VS_STRIDE) * 4)

__global__ __launch_bounds__(128, 4)
void attn_tc(const float* __restrict__ qkv, const float* __restrict__ gv,
             float* __restrict__ Y)
{
    extern __shared__ float sm[];
    float* Ks = sm;                          // [2][64][KS_STRIDE]
    float* Vt = sm + 2 * 64 * KS_STRIDE;     // [64][VS_STRIDE]  (d-major)

    const int bid = blockIdx.x;
    const int qb  = (Tc / 64 - 1) - (bid >> 5);  // heavy blocks first
    const int bh  = bid & 31;
    const int b   = bh >> 4;
    const int h   = bh & 15;
    const int tid = threadIdx.x;
    const int lane = tid & 31, wid = tid >> 5;
    const int wm  = wid * 16;
    const int g   = lane >> 2, tq = lane & 3;
    const int qg0 = qb * 64;

    const float* qptr = qkv + (size_t)(b * Tc) * N1 + h * HD;
    const float* kptr = qptr + Cc;
    const float* vhead = gv + ((size_t)(b * NH + h)) * HD * Tc;

    const int krow  = tid >> 1;
    const int kcol0 = (tid & 1) * 32;

    auto load_k = [&](int jt, int buf) {
        const float* pk = kptr + (size_t)(jt * 64 + krow) * N1 + kcol0;
        uint32_t dk = smem_u32(&Ks[(buf * 64 + krow) * KS_STRIDE + kcol0]);
#pragma unroll
        for (int c = 0; c < 8; c++) cp16(dk + 16 * c, pk + 4 * c);
    };
    auto load_v = [&](int jt) {
        const float* pv = vhead + (size_t)krow * Tc + jt * 64 + kcol0;
        uint32_t dv = smem_u32(&Vt[krow * VS_STRIDE + kcol0]);
#pragma unroll
        for (int c = 0; c < 8; c++) cp16(dv + 16 * c, pv + 4 * c);
    };

    load_k(0, 0);
    cp_commit();

    // Q fragments from gmem (q-part is P4' on d; *0.125 exact in tf32)
    unsigned qa[8][4];
    {
        const float* q0 = qptr + (size_t)(qg0 + wm + g) * N1;
        const float* q1 = q0 + 8 * (size_t)N1;
#pragma unroll
        for (int kb = 0; kb < 8; kb++) {
            float2 f0 = *(const float2*)&q0[kb * 8 + tq * 2];
            float2 f1 = *(const float2*)&q1[kb * 8 + tq * 2];
            qa[kb][0] = __float_as_uint(f0.x * 0.125f);
            qa[kb][1] = __float_as_uint(f1.x * 0.125f);
            qa[kb][2] = __float_as_uint(f0.y * 0.125f);
            qa[kb][3] = __float_as_uint(f1.y * 0.125f);
        }
    }

    float o[8][4];
#pragma unroll
    for (int nt = 0; nt < 8; nt++)
#pragma unroll
        for (int i = 0; i < 4; i++) o[nt][i] = 0.f;
    float m_lo = -INFINITY, m_hi = -INFINITY, l_lo = 0.f, l_hi = 0.f;

    const int r_lo = qg0 + wm + g;
    const int r_hi = r_lo + 8;
    const int srcA = (lane & ~3) | (tq >> 1);
    const int srcB = srcA + 2;
    const bool odd = (tq & 1);

    for (int jt = 0; jt <= qb; jt++) {
        const int cur = jt & 1;
        const bool hn = jt < qb;
        load_v(jt); cp_commit();
        if (hn) { load_k(jt + 1, cur ^ 1); cp_commit(); cp_wait<2>(); }
        else    { cp_wait<1>(); }
        __syncthreads();   // K(jt) visible; prev-iter Vt readers done

        const float* bK = Ks + (size_t)cur * 64 * KS_STRIDE;

        // S = Q @ K^T  (K d-cols P4': pair (tq, tq+4) -> LDS.64)
        float sc[8][4];
#pragma unroll
        for (int nt = 0; nt < 8; nt++) {
#pragma unroll
            for (int i = 0; i < 4; i++) sc[nt][i] = 0.f;
            const float* kr = &bK[(nt * 8 + g) * KS_STRIDE + tq * 2];
#pragma unroll
            for (int kb = 0; kb < 8; kb++) {
                float2 kf = *(const float2*)&kr[kb * 8];
                mma_tf32(sc[nt], qa[kb],
                         __float_as_uint(kf.x), __float_as_uint(kf.y));
            }
        }

        // causal mask on the diagonal tile
        if (jt == qb) {
#pragma unroll
            for (int nt = 0; nt < 8; nt++) {
                const int c = qg0 + nt * 8 + 2 * tq;
                if (c     > r_lo) sc[nt][0] = -INFINITY;
                if (c + 1 > r_lo) sc[nt][1] = -INFINITY;
                if (c     > r_hi) sc[nt][2] = -INFINITY;
                if (c + 1 > r_hi) sc[nt][3] = -INFINITY;
            }
        }

        // online softmax
        float tmax_lo = -INFINITY, tmax_hi = -INFINITY;
#pragma unroll
        for (int nt = 0; nt < 8; nt++) {
            tmax_lo = fmaxf(tmax_lo, fmaxf(sc[nt][0], sc[nt][1]));
            tmax_hi = fmaxf(tmax_hi, fmaxf(sc[nt][2], sc[nt][3]));
        }
        tmax_lo = fmaxf(tmax_lo, __shfl_xor_sync(0xffffffffu, tmax_lo, 1));
        tmax_lo = fmaxf(tmax_lo, __shfl_xor_sync(0xffffffffu, tmax_lo, 2));
        tmax_hi = fmaxf(tmax_hi, __shfl_xor_sync(0xffffffffu, tmax_hi, 1));
        tmax_hi = fmaxf(tmax_hi, __shfl_xor_sync(0xffffffffu, tmax_hi, 2));

        const float mn_lo = fmaxf(m_lo, tmax_lo);
        const float mn_hi = fmaxf(m_hi, tmax_hi);
        const float corr_lo = __expf(m_lo - mn_lo);
        const float corr_hi = __expf(m_hi - mn_hi);
        m_lo = mn_lo; m_hi = mn_hi;

        float ls_lo = 0.f, ls_hi = 0.f;
#pragma unroll
        for (int nt = 0; nt < 8; nt++) {
            float p0 = __expf(sc[nt][0] - mn_lo);
            float p1 = __expf(sc[nt][1] - mn_lo);
            float p2 = __expf(sc[nt][2] - mn_hi);
            float p3 = __expf(sc[nt][3] - mn_hi);
            ls_lo += p0 + p1;
            ls_hi += p2 + p3;
            sc[nt][0] = f2tf(p0); sc[nt][1] = f2tf(p1);
            sc[nt][2] = f2tf(p2); sc[nt][3] = f2tf(p3);
        }
        ls_lo += __shfl_xor_sync(0xffffffffu, ls_lo, 1);
        ls_lo += __shfl_xor_sync(0xffffffffu, ls_lo, 2);
        ls_hi += __shfl_xor_sync(0xffffffffu, ls_hi, 1);
        ls_hi += __shfl_xor_sync(0xffffffffu, ls_hi, 2);
        l_lo = l_lo * corr_lo + ls_lo;
        l_hi = l_hi * corr_hi + ls_hi;

#pragma unroll
        for (int nt = 0; nt < 8; nt++) {
            o[nt][0] *= corr_lo; o[nt][1] *= corr_lo;
            o[nt][2] *= corr_hi; o[nt][3] *= corr_hi;
        }

        if (hn) cp_wait<1>(); else cp_wait<0>();
        __syncthreads();   // Vt(jt) visible

        // O += P @ V. P A-frags via quad shuffles; V B-frags: Vt row (d) with
        // P4' on t -> pair (tq, tq+4) adjacent -> LDS.64.
#pragma unroll
        for (int kb = 0; kb < 8; kb++) {
            float e0A = __shfl_sync(0xffffffffu, sc[kb][0], srcA);
            float e1A = __shfl_sync(0xffffffffu, sc[kb][1], srcA);
            float e2A = __shfl_sync(0xffffffffu, sc[kb][2], srcA);
            float e3A = __shfl_sync(0xffffffffu, sc[kb][3], srcA);
            float e0B = __shfl_sync(0xffffffffu, sc[kb][0], srcB);
            float e1B = __shfl_sync(0xffffffffu, sc[kb][1], srcB);
            float e2B = __shfl_sync(0xffffffffu, sc[kb][2], srcB);
            float e3B = __shfl_sync(0xffffffffu, sc[kb][3], srcB);
            unsigned pa[4];
            pa[0] = __float_as_uint(odd ? e1A : e0A);
            pa[1] = __float_as_uint(odd ? e3A : e2A);
            pa[2] = __float_as_uint(odd ? e1B : e0B);
            pa[3] = __float_as_uint(odd ? e3B : e2B);
            const int kp = kb * 8 + tq * 2;
#pragma unroll
            for (int nt = 0; nt < 8; nt++) {
                float2 vf = *(const float2*)&Vt[(nt * 8 + g) * VS_STRIDE + kp];
                mma_tf32(o[nt], pa,
                         __float_as_uint(vf.x), __float_as_uint(vf.y));
            }
        }
        __syncthreads();   // Vt readers done before next iter's load_v
    }

    // write Y with P4' on the d columns (consumed by GEMM2 / lora_a)
    const float inv_lo = 1.f / l_lo;
    const float inv_hi = 1.f / l_hi;
    const int p0 = 4 * (tq & 1) + (tq >> 1);   // perm of col 2tq within 8-group
#pragma unroll
    for (int nt = 0; nt < 8; nt++) {
        const int cb = h * HD + nt * 8;
        float* y0 = &Y[(size_t)(b * Tc + r_lo) * Cc + cb];
        float* y1 = &Y[(size_t)(b * Tc + r_hi) * Cc + cb];
        y0[p0]     = f2tf(o[nt][0] * inv_lo);
        y0[p0 + 2] = f2tf(o[nt][1] * inv_lo);
        y1[p0]     = f2tf(o[nt][2] * inv_hi);
        y1[p0 + 2] = f2tf(o[nt][3] * inv_hi);
    }
}

// ---------------------------------------------------------------------------
// Launcher
// ---------------------------------------------------------------------------
extern "C" void kernel_launch(void* const* d_in, const int* in_sizes, int n_in,
                              void* d_out, int out_size)
{
    const float* x        = (const float*)d_in[0];
    const float* w_attn   = (const float*)d_in[1];
    const float* b_attn   = (const float*)d_in[2];
    const float* la_attn  = (const float*)d_in[3];
    const float* lb_attn  = (const float*)d_in[4];
    const float* w_proj   = (const float*)d_in[5];
    const float* b_proj   = (const float*)d_in[6];
    const float* la_proj  = (const float*)d_in[7];
    const float* lb_proj  = (const float*)d_in[8];
    float* out            = (float*)d_out;

    float *qkv, *gv, *y, *xa, *ya, *xc, *w1c, *w2c, *lb1c, *lb2c, *la2c;
    cudaGetSymbolAddress((void**)&qkv,  g_qkv);
    cudaGetSymbolAddress((void**)&gv,   g_v);
    cudaGetSymbolAddress((void**)&y,    g_y);
    cudaGetSymbolAddress((void**)&xa,   g_xa);
    cudaGetSymbolAddress((void**)&ya,   g_ya);
    cudaGetSymbolAddress((void**)&xc,   g_xc);
    cudaGetSymbolAddress((void**)&w1c,  g_w1c);
    cudaGetSymbolAddress((void**)&w2c,  g_w2c);
    cudaGetSymbolAddress((void**)&lb1c, g_lb1c);
    cudaGetSymbolAddress((void**)&lb2c, g_lb2c);
    cudaGetSymbolAddress((void**)&la2c, g_la2c);

    cudaFuncSetAttribute(gemm_lora_tc<0>,
                         cudaFuncAttributeMaxDynamicSharedMemorySize, GEMM_SMEM);
    cudaFuncSetAttribute(gemm_lora_tc<1>,
                         cudaFuncAttributeMaxDynamicSharedMemorySize, GEMM_SMEM);
    cudaFuncSetAttribute(attn_tc,
                         cudaFuncAttributeMaxDynamicSharedMemorySize, ATTN_SMEM);

    // 0. tf32 + P4' pre-conversion
    prep_kernel<<<2048, 256>>>((const float4*)x, (const float4*)w_attn,
                               (const float4*)w_proj, (const float4*)lb_attn,
                               (const float4*)lb_proj, (const float4*)la_proj,
                               xc, w1c, w2c, lb1c, lb2c, la2c);

    // 1. xa = x @ A_attn^T (raw x, raw A: permutation-invariant dot)
    lora_a_kernel<<<Mtot / 8, 256>>>(x, la_attn, xa);

    // 2. qkv(q,k P4') + gv(v transposed) = [x|xa] @ [W|LB*s]^T + b
    {
        dim3 grid(N1 / GBN, Mtot / 128);
        gemm_lora_tc<0><<<grid, 256, GEMM_SMEM>>>(
            xc, w1c, b_attn, xa, lb1c, qkv, gv, N1);
    }

    // 3. attention -> y (P4' cols, tf32)
    attn_tc<<<(Tc / 64) * Bc * NH, 128, ATTN_SMEM>>>(qkv, gv, y);

    // 4. ya = y @ A_proj^T (both P4'-permuted)
    lora_a_kernel<<<Mtot / 8, 256>>>(y, la2c, ya);

    // 5. out = [y|ya] @ [W|LB*s]^T + b (plain fp32 output)
    {
        dim3 grid(Cc / GBN, Mtot / 128);
        gemm_lora_tc<1><<<grid, 256, GEMM_SMEM>>>(
            y, w2c, b_proj, ya, lb2c, out, gv, Cc);
    }
}

// round 7
// speedup vs baseline: 2.3129x; 2.0258x over previous
#include <cuda_runtime.h>
#include <cuda_fp16.h>
#include <math.h>
#include <stdint.h>

// Problem constants (fixed by setup_inputs)
#define Bc   2
#define Tc   2048
#define Cc   1024
#define NH   16
#define HD   64
#define Mtot (Bc * Tc)        // 4096
#define N1   (3 * Cc)         // 3072
#define Kc   Cc               // 1024
#define Rr   16
#define LORA_SCALE (1.0f / 16.0f)

// Scratch (device globals: allocation-free rule). All fp16 tensors use the
// pair-interleaved K layout: within each 16-group, pair p -> 2*(p&3)+(p>>2).
__device__ __half g_qk[Mtot * 2048];        // [t][ q(1024) | k(1024) ], 16 MB
__device__ __half g_v [Bc * NH * HD * Tc];  // [b,h,d][t_perm], 8 MB
__device__ __half g_y [Mtot * Cc];          // attention out, 8 MB
__device__ __half g_xa[Mtot * Rr];
__device__ __half g_ya[Mtot * Rr];
__device__ __half g_xh [Mtot * Kc];         // x (perm)
__device__ __half g_w1h[N1 * Kc];           // w_attn (perm)
__device__ __half g_w2h[Cc * Kc];           // w_proj (perm)
__device__ __half g_lb1h[N1 * Rr];          // lora_b_attn * scale (perm)
__device__ __half g_lb2h[Cc * Rr];          // lora_b_proj * scale (perm)
__device__ float  g_la2c[Rr * Kc];          // lora_a_proj fp32 (perm)

// ---------------------------------------------------------------------------
// helpers
// ---------------------------------------------------------------------------
__device__ __forceinline__ int pperm(int j) {   // j in [0,16)
    int p = j >> 1, e = j & 1;
    return 4 * (p & 3) + 2 * (p >> 2) + e;
}

__device__ __forceinline__ unsigned h2u(half2 h) {
    union { half2 h; unsigned u; } c;
    c.h = h;
    return c.u;
}

__device__ __forceinline__ void mma_f16(float* d, const unsigned* a,
                                        unsigned b0, unsigned b1) {
    asm volatile(
        "mma.sync.aligned.m16n8k16.row.col.f32.f16.f16.f32 "
        "{%0,%1,%2,%3},{%4,%5,%6,%7},{%8,%9},{%0,%1,%2,%3};\n"
        : "+f"(d[0]), "+f"(d[1]), "+f"(d[2]), "+f"(d[3])
        : "r"(a[0]), "r"(a[1]), "r"(a[2]), "r"(a[3]), "r"(b0), "r"(b1));
}

__device__ __forceinline__ uint32_t smem_u32(const void* p) {
    return (uint32_t)__cvta_generic_to_shared(p);
}
__device__ __forceinline__ void cp16(uint32_t dst, const void* src) {
    asm volatile("cp.async.ca.shared.global [%0], [%1], 16;" :: "r"(dst), "l"(src));
}
__device__ __forceinline__ void cp_commit() {
    asm volatile("cp.async.commit_group;");
}
template <int N> __device__ __forceinline__ void cp_wait() {
    asm volatile("cp.async.wait_group %0;" :: "n"(N));
}

// ---------------------------------------------------------------------------
// prep: fp16-convert + pair-permute x, w_attn, w_proj, scaled lora_b's;
// fp32 pair-permute lora_a_proj.
// ---------------------------------------------------------------------------
#define NX4   (Mtot * Kc / 4)
#define NW14  (N1 * Kc / 4)
#define NW24  (Cc * Kc / 4)
#define NL14  (N1 * Rr / 4)
#define NL24  (Cc * Rr / 4)
#define NA24  (Rr * Kc / 4)
#define NTOT4 (NX4 + NW14 + NW24 + NL14 + NL24 + NA24)

__global__ __launch_bounds__(256)
void prep_kernel(const float4* __restrict__ x,  const float4* __restrict__ w1,
                 const float4* __restrict__ w2, const float4* __restrict__ l1,
                 const float4* __restrict__ l2, const float4* __restrict__ la2,
                 __half* __restrict__ xh,  __half* __restrict__ w1h,
                 __half* __restrict__ w2h, __half* __restrict__ l1h,
                 __half* __restrict__ l2h, float* __restrict__ la2c)
{
    for (int i = blockIdx.x * blockDim.x + threadIdx.x; i < NTOT4;
         i += gridDim.x * blockDim.x) {
        float4 v; __half* dsth = nullptr; float* dstf = nullptr;
        int loc; float s = 1.f;
        int j = i;
        if (j < NX4)                { v = x[j];  dsth = xh;  loc = j; }
        else if ((j -= NX4) < NW14) { v = w1[j]; dsth = w1h; loc = j; }
        else if ((j -= NW14) < NW24){ v = w2[j]; dsth = w2h; loc = j; }
        else if ((j -= NW24) < NL14){ v = l1[j]; dsth = l1h; loc = j; s = LORA_SCALE; }
        else if ((j -= NL14) < NL24){ v = l2[j]; dsth = l2h; loc = j; s = LORA_SCALE; }
        else { j -= NL24;            v = la2[j]; dstf = la2c; loc = j; }

        const int flat = loc * 4;
        const int base = flat & ~15;
        const int j0   = flat & 15;        // 0,4,8,12
        if (dsth) {
            half2 h01 = __floats2half2_rn(v.x * s, v.y * s);
            half2 h23 = __floats2half2_rn(v.z * s, v.w * s);
            *(half2*)&dsth[base + pperm(j0)]     = h01;
            *(half2*)&dsth[base + pperm(j0 + 2)] = h23;
        } else {
            int p0 = pperm(j0), p2 = pperm(j0 + 2);
            dstf[base + p0]     = v.x; dstf[base + p0 + 1] = v.y;
            dstf[base + p2]     = v.z; dstf[base + p2 + 1] = v.w;
        }
    }
}

// ---------------------------------------------------------------------------
// LoRA A projections -> fp16 pair-permuted XA rows (16 values).
// Variant F: fp32 X (raw) with raw fp32 A. Variant H: fp16 X with fp32 A,
// both sharing the same pair-permuted K order.
// ---------------------------------------------------------------------------
__global__ __launch_bounds__(256)
void lora_a_f(const float* __restrict__ X, const float* __restrict__ Aw,
              __half* __restrict__ XA)
{
    const int lane = threadIdx.x & 31;
    const int w    = threadIdx.x >> 5;
    const int m    = blockIdx.x * 8 + w;

    float acc[Rr];
#pragma unroll
    for (int r = 0; r < Rr; r++) acc[r] = 0.f;

    const float* xr = X + (size_t)m * Kc;
#pragma unroll
    for (int it = 0; it < 8; it++) {
        int k = (it * 32 + lane) * 4;
        float4 xv = *(const float4*)&xr[k];
#pragma unroll
        for (int r = 0; r < Rr; r++) {
            float4 av = *(const float4*)&Aw[r * Kc + k];
            acc[r] += xv.x * av.x + xv.y * av.y + xv.z * av.z + xv.w * av.w;
        }
    }
#pragma unroll
    for (int r = 0; r < Rr; r++) {
        float v = acc[r];
#pragma unroll
        for (int off = 16; off; off >>= 1) v += __shfl_xor_sync(0xffffffffu, v, off);
        acc[r] = v;
    }
    if (lane == 0) {
        __half tmp[16];
#pragma unroll
        for (int r = 0; r < Rr; r++) tmp[pperm(r)] = __float2half_rn(acc[r]);
        *(uint4*)&XA[(size_t)m * Rr]     = *(uint4*)&tmp[0];
        *(uint4*)&XA[(size_t)m * Rr + 8] = *(uint4*)&tmp[8];
    }
}

__global__ __launch_bounds__(256)
void lora_a_h(const __half* __restrict__ X, const float* __restrict__ Aw,
              __half* __restrict__ XA)
{
    const int lane = threadIdx.x & 31;
    const int w    = threadIdx.x >> 5;
    const int m    = blockIdx.x * 8 + w;

    float acc[Rr];
#pragma unroll
    for (int r = 0; r < Rr; r++) acc[r] = 0.f;

    const __half* xr = X + (size_t)m * Kc;
#pragma unroll
    for (int it = 0; it < 4; it++) {
        int k = (it * 32 + lane) * 8;
        uint4 u = *(const uint4*)&xr[k];
        const half2* hp = (const half2*)&u;
        float2 f0 = __half22float2(hp[0]);
        float2 f1 = __half22float2(hp[1]);
        float2 f2 = __half22float2(hp[2]);
        float2 f3 = __half22float2(hp[3]);
#pragma unroll
        for (int r = 0; r < Rr; r++) {
            float4 a0 = *(const float4*)&Aw[r * Kc + k];
            float4 a1 = *(const float4*)&Aw[r * Kc + k + 4];
            acc[r] += f0.x * a0.x + f0.y * a0.y + f1.x * a0.z + f1.y * a0.w
                    + f2.x * a1.x + f2.y * a1.y + f3.x * a1.z + f3.y * a1.w;
        }
    }
#pragma unroll
    for (int r = 0; r < Rr; r++) {
        float v = acc[r];
#pragma unroll
        for (int off = 16; off; off >>= 1) v += __shfl_xor_sync(0xffffffffu, v, off);
        acc[r] = v;
    }
    if (lane == 0) {
        __half tmp[16];
#pragma unroll
        for (int r = 0; r < Rr; r++) tmp[pperm(r)] = __float2half_rn(acc[r]);
        *(uint4*)&XA[(size_t)m * Rr]     = *(uint4*)&tmp[0];
        *(uint4*)&XA[(size_t)m * Rr + 8] = *(uint4*)&tmp[8];
    }
}

// ---------------------------------------------------------------------------
// fp16 GEMM (m16n8k16), cp.async double-buffered, LoRA folded as final stage:
//   out = [A | XA] @ [W | LBs]^T + bias
// Block 128x128, BK=64 (16+1 stages), 256 threads, 8 warps (2x4), warp 64x32.
// smem stride 80 halves (160B) -> all LDS.64 conflict-free.
// MODE 0 epilogue: q (x0.125) / k -> g_qk fp16 perm; v -> g_v transposed.
// MODE 1 epilogue: plain fp32 + bias.
// ---------------------------------------------------------------------------
#define GBK   64
#define GSTRH 80
#define GBN   128
#define GEMM_SMEM (2 * (2 * 128 * GSTRH) * 2)   // 81920 bytes

template <int MODE>
__global__ __launch_bounds__(256, 2)
void gemm_lora_f16(const __half* __restrict__ A, const __half* __restrict__ W,
                   const float* __restrict__ bias, const __half* __restrict__ XA,
                   const __half* __restrict__ LBs, float* __restrict__ outf,
                   __half* __restrict__ qk, __half* __restrict__ gv, int N)
{
    extern __shared__ __half smh[];
    __half* sA = smh;                           // [2][128][GSTRH]
    __half* sW = smh + 2 * 128 * GSTRH;         // [2][128][GSTRH]

    const int tid  = threadIdx.x;
    const int row0 = blockIdx.y * 128;
    const int col0 = blockIdx.x * GBN;
    const int lane = tid & 31, wid = tid >> 5;
    const int wm = (wid >> 2) * 64;
    const int wn = (wid & 3) * 32;
    const int g  = lane >> 2, tq = lane & 3;

    const int arow = tid >> 1;
    const int ahalf = (tid & 1) * 32;           // 64B half-row

    float acc[4][4][4];
#pragma unroll
    for (int mt = 0; mt < 4; mt++)
#pragma unroll
        for (int nt = 0; nt < 4; nt++)
#pragma unroll
            for (int i = 0; i < 4; i++) acc[mt][nt][i] = 0.f;

    const int NMAIN = Kc / GBK;     // 16
    const int NST   = NMAIN + 1;

    auto load_main = [&](int s, int buf) {
        const __half* pa = A + (size_t)(row0 + arow) * Kc + s * GBK + ahalf;
        uint32_t da = smem_u32(&sA[(buf * 128 + arow) * GSTRH + ahalf]);
        cp16(da,      pa);      cp16(da + 16, pa + 8);
        cp16(da + 32, pa + 16); cp16(da + 48, pa + 24);
        const __half* pw = W + (size_t)(col0 + arow) * Kc + s * GBK + ahalf;
        uint32_t dw = smem_u32(&sW[(buf * 128 + arow) * GSTRH + ahalf]);
        cp16(dw,      pw);      cp16(dw + 16, pw + 8);
        cp16(dw + 32, pw + 16); cp16(dw + 48, pw + 24);
    };
    auto load_lora = [&](int buf) {
        const int r = tid >> 1;
        if ((tid & 1) == 0) {
            const __half* pa = XA + (size_t)(row0 + r) * Rr;
            uint32_t da = smem_u32(&sA[(buf * 128 + r) * GSTRH]);
            cp16(da, pa); cp16(da + 16, pa + 8);
        } else {
            const __half* pw = LBs + (size_t)(col0 + r) * Rr;
            uint32_t dw = smem_u32(&sW[(buf * 128 + r) * GSTRH]);
            cp16(dw, pw); cp16(dw + 16, pw + 8);
        }
    };
    auto compute = [&](int buf, int nsteps) {
        const __half* bA = sA + (size_t)buf * 128 * GSTRH;
        const __half* bW = sW + (size_t)buf * 128 * GSTRH;
        for (int ks = 0; ks < nsteps; ks++) {
            const int ko = ks * 16 + tq * 4;
            unsigned af[4][4], bf[4][2];
#pragma unroll
            for (int mt = 0; mt < 4; mt++) {
                const __half* rp = &bA[(wm + mt * 16 + g) * GSTRH + ko];
                uint2 lo = *(const uint2*)rp;
                uint2 hi = *(const uint2*)(rp + 8 * GSTRH);
                af[mt][0] = lo.x; af[mt][2] = lo.y;
                af[mt][1] = hi.x; af[mt][3] = hi.y;
            }
#pragma unroll
            for (int nt = 0; nt < 4; nt++) {
                uint2 bb = *(const uint2*)&bW[(wn + nt * 8 + g) * GSTRH + ko];
                bf[nt][0] = bb.x; bf[nt][1] = bb.y;
            }
#pragma unroll
            for (int mt = 0; mt < 4; mt++)
#pragma unroll
                for (int nt = 0; nt < 4; nt++)
                    mma_f16(acc[mt][nt], af[mt], bf[nt][0], bf[nt][1]);
        }
    };

    load_main(0, 0);
    cp_commit();

    for (int s = 0; s < NST; s++) {
        const int cur = s & 1;
        const bool hn = (s + 1 < NST);
        if (hn) {
            if (s + 1 < NMAIN) load_main(s + 1, cur ^ 1);
            else               load_lora(cur ^ 1);
            cp_commit();
            cp_wait<1>();
        } else {
            cp_wait<0>();
        }
        __syncthreads();
        compute(cur, (s < NMAIN) ? 4 : 1);
        __syncthreads();
    }

    // epilogue
#pragma unroll
    for (int nt = 0; nt < 4; nt++) {
        const int n = col0 + wn + nt * 8 + 2 * tq;   // even
        const float b0 = bias[n], b1 = bias[n + 1];
#pragma unroll
        for (int mt = 0; mt < 4; mt++) {
            const int r = row0 + wm + mt * 16 + g;
            float v0 = acc[mt][nt][0] + b0, v1 = acc[mt][nt][1] + b1;
            float v2 = acc[mt][nt][2] + b0, v3 = acc[mt][nt][3] + b1;
            if (MODE == 1) {
                float2 lo; lo.x = v0; lo.y = v1;
                *(float2*)&outf[(size_t)r * N + n] = lo;
                float2 hi; hi.x = v2; hi.y = v3;
                *(float2*)&outf[(size_t)(r + 8) * N + n] = hi;
            } else {
                if (n < 2 * Cc) {
                    const float s125 = (n < Cc) ? 0.125f : 1.f;
                    half2 lo = __floats2half2_rn(v0 * s125, v1 * s125);
                    half2 hi = __floats2half2_rn(v2 * s125, v3 * s125);
                    const int base = n & ~15, pos = pperm(n & 15);
                    *(half2*)&qk[(size_t)r * 2048 + base + pos]       = lo;
                    *(half2*)&qk[(size_t)(r + 8) * 2048 + base + pos] = hi;
                } else {
                    const int dg = n - 2 * Cc;
                    const int hh = dg >> 6, dd = dg & 63;
                    const int bb = r >> 11, t = r & (Tc - 1);
                    const int tb = t & ~15, tp = pperm(t & 15);
                    __half* vr0 = &gv[(((size_t)(bb * NH + hh)) * HD + dd) * Tc + tb];
                    __half* vr1 = vr0 + Tc;
                    vr0[tp]     = __float2half_rn(v0);
                    vr0[tp + 2] = __float2half_rn(v2);
                    vr1[tp]     = __float2half_rn(v1);
                    vr1[tp + 2] = __float2half_rn(v3);
                }
            }
        }
    }
}

// ---------------------------------------------------------------------------
// Flash attention, fp16 m16n8k16. K tiles [t][d_perm] (from g_qk), V tiles
// [d][t_perm] (g_v) -> every fragment is one conflict-free LDS.64. P goes
// from S C-frags to PV A-frags by register packing (no shuffles, no smem).
// K double-buffered, V single-buffered. ~30KB smem, 4 blocks/SM.
// ---------------------------------------------------------------------------
#define KSTRH 80
#define ATTN_SMEM ((2 * 64 * KSTRH + 64 * KSTRH) * 2)

__global__ __launch_bounds__(128, 4)
void attn_f16(const __half* __restrict__ qk, const __half* __restrict__ gv,
              __half* __restrict__ yh)
{
    extern __shared__ __half smh[];
    __half* Ks = smh;                        // [2][64][KSTRH]
    __half* Vt = smh + 2 * 64 * KSTRH;       // [64][KSTRH]

    const int bid = blockIdx.x;
    const int qb  = (Tc / 64 - 1) - (bid >> 5);  // heavy blocks first
    const int bh  = bid & 31;
    const int b   = bh >> 4;
    const int h   = bh & 15;
    const int tid = threadIdx.x;
    const int lane = tid & 31, wid = tid >> 5;
    const int wm  = wid * 16;
    const int g   = lane >> 2, tq = lane & 3;
    const int qg0 = qb * 64;

    const __half* qbase = qk + (size_t)(b * Tc) * 2048 + h * 64;
    const __half* kbase = qbase + 1024;
    const __half* vhead = gv + ((size_t)(b * NH + h)) * HD * Tc;

    const int krow  = tid >> 1;
    const int khalf = (tid & 1) * 32;

    auto load_k = [&](int jt, int buf) {
        const __half* pk = kbase + (size_t)(jt * 64 + krow) * 2048 + khalf;
        uint32_t dk = smem_u32(&Ks[(buf * 64 + krow) * KSTRH + khalf]);
        cp16(dk, pk);      cp16(dk + 16, pk + 8);
        cp16(dk + 32, pk + 16); cp16(dk + 48, pk + 24);
    };
    auto load_v = [&](int jt) {
        const __half* pv = vhead + (size_t)krow * Tc + jt * 64 + khalf;
        uint32_t dv = smem_u32(&Vt[krow * KSTRH + khalf]);
        cp16(dv, pv);      cp16(dv + 16, pv + 8);
        cp16(dv + 32, pv + 16); cp16(dv + 48, pv + 24);
    };

    load_k(0, 0);
    cp_commit();

    // Q fragments from gmem (q already scaled by 0.125 and d-permuted)
    unsigned qa[4][4];
    {
        const __half* q0 = qbase + (size_t)(qg0 + wm + g) * 2048;
        const __half* q1 = q0 + 8 * (size_t)2048;
#pragma unroll
        for (int kb = 0; kb < 4; kb++) {
            uint2 lo = *(const uint2*)&q0[kb * 16 + tq * 4];
            uint2 hi = *(const uint2*)&q1[kb * 16 + tq * 4];
            qa[kb][0] = lo.x; qa[kb][2] = lo.y;
            qa[kb][1] = hi.x; qa[kb][3] = hi.y;
        }
    }

    float o[8][4];
#pragma unroll
    for (int nt = 0; nt < 8; nt++)
#pragma unroll
        for (int i = 0; i < 4; i++) o[nt][i] = 0.f;
    float m_lo = -INFINITY, m_hi = -INFINITY, l_lo = 0.f, l_hi = 0.f;

    const int r_lo = qg0 + wm + g;
    const int r_hi = r_lo + 8;

    for (int jt = 0; jt <= qb; jt++) {
        const int cur = jt & 1;
        const bool hn = jt < qb;
        load_v(jt); cp_commit();
        if (hn) { load_k(jt + 1, cur ^ 1); cp_commit(); cp_wait<2>(); }
        else    { cp_wait<1>(); }
        __syncthreads();   // K(jt) visible; prev-iter Vt readers done

        const __half* bK = Ks + (size_t)cur * 64 * KSTRH;

        // S = Q @ K^T
        float sc[8][4];
#pragma unroll
        for (int nt = 0; nt < 8; nt++) {
#pragma unroll
            for (int i = 0; i < 4; i++) sc[nt][i] = 0.f;
            const __half* kr = &bK[(nt * 8 + g) * KSTRH + tq * 4];
#pragma unroll
            for (int kb = 0; kb < 4; kb++) {
                uint2 bb = *(const uint2*)&kr[kb * 16];
                mma_f16(sc[nt], qa[kb], bb.x, bb.y);
            }
        }

        // causal mask on the diagonal tile
        if (jt == qb) {
#pragma unroll
            for (int nt = 0; nt < 8; nt++) {
                const int c = qg0 + nt * 8 + 2 * tq;
                if (c     > r_lo) sc[nt][0] = -INFINITY;
                if (c + 1 > r_lo) sc[nt][1] = -INFINITY;
                if (c     > r_hi) sc[nt][2] = -INFINITY;
                if (c + 1 > r_hi) sc[nt][3] = -INFINITY;
            }
        }

        // online softmax (fp32)
        float tmax_lo = -INFINITY, tmax_hi = -INFINITY;
#pragma unroll
        for (int nt = 0; nt < 8; nt++) {
            tmax_lo = fmaxf(tmax_lo, fmaxf(sc[nt][0], sc[nt][1]));
            tmax_hi = fmaxf(tmax_hi, fmaxf(sc[nt][2], sc[nt][3]));
        }
        tmax_lo = fmaxf(tmax_lo, __shfl_xor_sync(0xffffffffu, tmax_lo, 1));
        tmax_lo = fmaxf(tmax_lo, __shfl_xor_sync(0xffffffffu, tmax_lo, 2));
        tmax_hi = fmaxf(tmax_hi, __shfl_xor_sync(0xffffffffu, tmax_hi, 1));
        tmax_hi = fmaxf(tmax_hi, __shfl_xor_sync(0xffffffffu, tmax_hi, 2));

        const float mn_lo = fmaxf(m_lo, tmax_lo);
        const float mn_hi = fmaxf(m_hi, tmax_hi);
        const float corr_lo = __expf(m_lo - mn_lo);
        const float corr_hi = __expf(m_hi - mn_hi);
        m_lo = mn_lo; m_hi = mn_hi;

        float ls_lo = 0.f, ls_hi = 0.f;
#pragma unroll
        for (int nt = 0; nt < 8; nt++) {
            sc[nt][0] = __expf(sc[nt][0] - mn_lo);
            sc[nt][1] = __expf(sc[nt][1] - mn_lo);
            sc[nt][2] = __expf(sc[nt][2] - mn_hi);
            sc[nt][3] = __expf(sc[nt][3] - mn_hi);
            ls_lo += sc[nt][0] + sc[nt][1];
            ls_hi += sc[nt][2] + sc[nt][3];
        }
        ls_lo += __shfl_xor_sync(0xffffffffu, ls_lo, 1);
        ls_lo += __shfl_xor_sync(0xffffffffu, ls_lo, 2);
        ls_hi += __shfl_xor_sync(0xffffffffu, ls_hi, 1);
        ls_hi += __shfl_xor_sync(0xffffffffu, ls_hi, 2);
        l_lo = l_lo * corr_lo + ls_lo;
        l_hi = l_hi * corr_hi + ls_hi;

#pragma unroll
        for (int nt = 0; nt < 8; nt++) {
            o[nt][0] *= corr_lo; o[nt][1] *= corr_lo;
            o[nt][2] *= corr_hi; o[nt][3] *= corr_hi;
        }

        if (hn) cp_wait<1>(); else cp_wait<0>();
        __syncthreads();   // Vt(jt) visible

        // O += P @ V. PV A-frags = register packs of S C-frags (layout match).
#pragma unroll
        for (int kb = 0; kb < 4; kb++) {
            unsigned pa[4];
            pa[0] = h2u(__floats2half2_rn(sc[2*kb][0],   sc[2*kb][1]));
            pa[1] = h2u(__floats2half2_rn(sc[2*kb][2],   sc[2*kb][3]));
            pa[2] = h2u(__floats2half2_rn(sc[2*kb+1][0], sc[2*kb+1][1]));
            pa[3] = h2u(__floats2half2_rn(sc[2*kb+1][2], sc[2*kb+1][3]));
            const int ko = kb * 16 + tq * 4;
#pragma unroll
            for (int nt = 0; nt < 8; nt++) {
                uint2 vv = *(const uint2*)&Vt[(nt * 8 + g) * KSTRH + ko];
                mma_f16(o[nt], pa, vv.x, vv.y);
            }
        }
        __syncthreads();   // Vt readers done before next iter's load_v
    }

    // write y (fp16, d pair-permuted) for GEMM2 / lora_a_h
    const float inv_lo = 1.f / l_lo;
    const float inv_hi = 1.f / l_hi;
#pragma unroll
    for (int nt = 0; nt < 8; nt++) {
        const int c = h * 64 + nt * 8 + 2 * tq;     // even
        const int base = c & ~15, pos = pperm(c & 15);
        half2 lo = __floats2half2_rn(o[nt][0] * inv_lo, o[nt][1] * inv_lo);
        half2 hi = __floats2half2_rn(o[nt][2] * inv_hi, o[nt][3] * inv_hi);
        *(half2*)&yh[(size_t)(b * Tc + r_lo) * Cc + base + pos] = lo;
        *(half2*)&yh[(size_t)(b * Tc + r_hi) * Cc + base + pos] = hi;
    }
}

// ---------------------------------------------------------------------------
// Launcher
// ---------------------------------------------------------------------------
extern "C" void kernel_launch(void* const* d_in, const int* in_sizes, int n_in,
                              void* d_out, int out_size)
{
    const float* x        = (const float*)d_in[0];
    const float* w_attn   = (const float*)d_in[1];
    const float* b_attn   = (const float*)d_in[2];
    const float* la_attn  = (const float*)d_in[3];
    const float* lb_attn  = (const float*)d_in[4];
    const float* w_proj   = (const float*)d_in[5];
    const float* b_proj   = (const float*)d_in[6];
    const float* la_proj  = (const float*)d_in[7];
    const float* lb_proj  = (const float*)d_in[8];
    float* out            = (float*)d_out;

    __half *qk, *gv, *yh, *xa, *ya, *xh, *w1h, *w2h, *lb1h, *lb2h;
    float *la2c;
    cudaGetSymbolAddress((void**)&qk,   g_qk);
    cudaGetSymbolAddress((void**)&gv,   g_v);
    cudaGetSymbolAddress((void**)&yh,   g_y);
    cudaGetSymbolAddress((void**)&xa,   g_xa);
    cudaGetSymbolAddress((void**)&ya,   g_ya);
    cudaGetSymbolAddress((void**)&xh,   g_xh);
    cudaGetSymbolAddress((void**)&w1h,  g_w1h);
    cudaGetSymbolAddress((void**)&w2h,  g_w2h);
    cudaGetSymbolAddress((void**)&lb1h, g_lb1h);
    cudaGetSymbolAddress((void**)&lb2h, g_lb2h);
    cudaGetSymbolAddress((void**)&la2c, g_la2c);

    cudaFuncSetAttribute(gemm_lora_f16<0>,
                         cudaFuncAttributeMaxDynamicSharedMemorySize, GEMM_SMEM);
    cudaFuncSetAttribute(gemm_lora_f16<1>,
                         cudaFuncAttributeMaxDynamicSharedMemorySize, GEMM_SMEM);
    cudaFuncSetAttribute(attn_f16,
                         cudaFuncAttributeMaxDynamicSharedMemorySize, ATTN_SMEM);

    // 0. fp16 + pair-perm pre-conversion
    prep_kernel<<<2048, 256>>>((const float4*)x, (const float4*)w_attn,
                               (const float4*)w_proj, (const float4*)lb_attn,
                               (const float4*)lb_proj, (const float4*)la_proj,
                               xh, w1h, w2h, lb1h, lb2h, la2c);

    // 1. xa = x @ A_attn^T (raw fp32 inputs; perm-invariant dot)
    lora_a_f<<<Mtot / 8, 256>>>(x, la_attn, xa);

    // 2. q(x0.125),k -> g_qk; v -> g_v transposed
    {
        dim3 grid(N1 / GBN, Mtot / 128);
        gemm_lora_f16<0><<<grid, 256, GEMM_SMEM>>>(
            xh, w1h, b_attn, xa, lb1h, nullptr, qk, gv, N1);
    }

    // 3. attention -> y (fp16, perm)
    attn_f16<<<(Tc / 64) * Bc * NH, 128, ATTN_SMEM>>>(qk, gv, yh);

    // 4. ya = y @ A_proj^T (fp16 y, matching-perm fp32 A)
    lora_a_h<<<Mtot / 8, 256>>>(yh, la2c, ya);

    // 5. out = [y|ya] @ [W|LB*s]^T + b (fp32 output)
    {
        dim3 grid(Cc / GBN, Mtot / 128);
        gemm_lora_f16<1><<<grid, 256, GEMM_SMEM>>>(
            yh, w2h, b_proj, ya, lb2h, out, nullptr, nullptr, Cc);
    }
}

// round 8
// speedup vs baseline: 2.4679x; 1.0670x over previous
#include <cuda_runtime.h>
#include <cuda_fp16.h>
#include <math.h>
#include <stdint.h>

// Problem constants (fixed by setup_inputs)
#define Bc   2
#define Tc   2048
#define Cc   1024
#define NH   16
#define HD   64
#define Mtot (Bc * Tc)        // 4096
#define N1   (3 * Cc)         // 3072
#define Kc   Cc               // 1024
#define Rr   16
#define LORA_SCALE (1.0f / 16.0f)
#define QSCALE 0.18033688011112042f   // 0.125 * log2(e)

// Scratch (device globals: allocation-free rule). All fp16 tensors use the
// pair-interleaved K layout: within each 16-group, pair p -> 2*(p&3)+(p>>2).
__device__ __half g_qk[Mtot * 2048];        // [t][ q(1024) | k(1024) ], 16 MB
__device__ __half g_v [Bc * NH * HD * Tc];  // [b,h,d][t_perm], 8 MB
__device__ __half g_y [Mtot * Cc];          // attention out, 8 MB
__device__ __half g_xa[Mtot * Rr];
__device__ __half g_ya[Mtot * Rr];
__device__ __half g_xh [Mtot * Kc];         // x (perm)
__device__ __half g_w1h[N1 * Kc];           // w_attn (perm)
__device__ __half g_w2h[Cc * Kc];           // w_proj (perm)
__device__ __half g_lb1h[N1 * Rr];          // lora_b_attn * scale (perm)
__device__ __half g_lb2h[Cc * Rr];          // lora_b_proj * scale (perm)
__device__ __half g_la1h[Rr * Kc];          // lora_a_attn (perm, fp16)
__device__ __half g_la2h[Rr * Kc];          // lora_a_proj (perm, fp16)

// ---------------------------------------------------------------------------
// helpers
// ---------------------------------------------------------------------------
__device__ __forceinline__ int pperm(int j) {   // j in [0,16)
    int p = j >> 1, e = j & 1;
    return 4 * (p & 3) + 2 * (p >> 2) + e;
}

__device__ __forceinline__ unsigned h2u(half2 h) {
    union { half2 h; unsigned u; } c;
    c.h = h;
    return c.u;
}

__device__ __forceinline__ float fex2(float x) {
    float y;
    asm("ex2.approx.ftz.f32 %0, %1;" : "=f"(y) : "f"(x));
    return y;
}

__device__ __forceinline__ void mma_f16(float* d, const unsigned* a,
                                        unsigned b0, unsigned b1) {
    asm volatile(
        "mma.sync.aligned.m16n8k16.row.col.f32.f16.f16.f32 "
        "{%0,%1,%2,%3},{%4,%5,%6,%7},{%8,%9},{%0,%1,%2,%3};\n"
        : "+f"(d[0]), "+f"(d[1]), "+f"(d[2]), "+f"(d[3])
        : "r"(a[0]), "r"(a[1]), "r"(a[2]), "r"(a[3]), "r"(b0), "r"(b1));
}

__device__ __forceinline__ uint32_t smem_u32(const void* p) {
    return (uint32_t)__cvta_generic_to_shared(p);
}
__device__ __forceinline__ void cp16(uint32_t dst, const void* src) {
    asm volatile("cp.async.ca.shared.global [%0], [%1], 16;" :: "r"(dst), "l"(src));
}
__device__ __forceinline__ void cp_commit() {
    asm volatile("cp.async.commit_group;");
}
template <int N> __device__ __forceinline__ void cp_wait() {
    asm volatile("cp.async.wait_group %0;" :: "n"(N));
}

// ---------------------------------------------------------------------------
// prep: fp16-convert + pair-permute x, w_attn, w_proj, scaled lora_b's,
// and both lora_a matrices.
// ---------------------------------------------------------------------------
#define NX4   (Mtot * Kc / 4)
#define NW14  (N1 * Kc / 4)
#define NW24  (Cc * Kc / 4)
#define NL14  (N1 * Rr / 4)
#define NL24  (Cc * Rr / 4)
#define NA4   (Rr * Kc / 4)
#define NTOT4 (NX4 + NW14 + NW24 + NL14 + NL24 + 2 * NA4)

__global__ __launch_bounds__(256)
void prep_kernel(const float4* __restrict__ x,  const float4* __restrict__ w1,
                 const float4* __restrict__ w2, const float4* __restrict__ l1,
                 const float4* __restrict__ l2, const float4* __restrict__ la1,
                 const float4* __restrict__ la2,
                 __half* __restrict__ xh,  __half* __restrict__ w1h,
                 __half* __restrict__ w2h, __half* __restrict__ l1h,
                 __half* __restrict__ l2h, __half* __restrict__ la1h,
                 __half* __restrict__ la2h)
{
    for (int i = blockIdx.x * blockDim.x + threadIdx.x; i < NTOT4;
         i += gridDim.x * blockDim.x) {
        float4 v; __half* dsth; int loc; float s = 1.f;
        int j = i;
        if (j < NX4)                { v = x[j];   dsth = xh;   loc = j; }
        else if ((j -= NX4) < NW14) { v = w1[j];  dsth = w1h;  loc = j; }
        else if ((j -= NW14) < NW24){ v = w2[j];  dsth = w2h;  loc = j; }
        else if ((j -= NW24) < NL14){ v = l1[j];  dsth = l1h;  loc = j; s = LORA_SCALE; }
        else if ((j -= NL14) < NL24){ v = l2[j];  dsth = l2h;  loc = j; s = LORA_SCALE; }
        else if ((j -= NL24) < NA4) { v = la1[j]; dsth = la1h; loc = j; }
        else { j -= NA4;             v = la2[j];  dsth = la2h; loc = j; }

        const int flat = loc * 4;
        const int base = flat & ~15;
        const int j0   = flat & 15;        // 0,4,8,12
        half2 h01 = __floats2half2_rn(v.x * s, v.y * s);
        half2 h23 = __floats2half2_rn(v.z * s, v.w * s);
        *(half2*)&dsth[base + pperm(j0)]     = h01;
        *(half2*)&dsth[base + pperm(j0 + 2)] = h23;
    }
}

// ---------------------------------------------------------------------------
// LoRA A projection: XA[m,r] = sum_k X[m,k] * A[r,k]; fp16 inputs (matching
// pair-permuted K order on both sides), fp32 accumulate, fp16 perm output.
// ---------------------------------------------------------------------------
__global__ __launch_bounds__(256)
void lora_a_h(const __half* __restrict__ X, const __half* __restrict__ Aw,
              __half* __restrict__ XA)
{
    const int lane = threadIdx.x & 31;
    const int w    = threadIdx.x >> 5;
    const int m    = blockIdx.x * 8 + w;

    float acc[Rr];
#pragma unroll
    for (int r = 0; r < Rr; r++) acc[r] = 0.f;

    const __half* xr = X + (size_t)m * Kc;
#pragma unroll
    for (int it = 0; it < 4; it++) {
        int k = (it * 32 + lane) * 8;
        uint4 u = *(const uint4*)&xr[k];
        const half2* hx = (const half2*)&u;
        float2 fx0 = __half22float2(hx[0]);
        float2 fx1 = __half22float2(hx[1]);
        float2 fx2 = __half22float2(hx[2]);
        float2 fx3 = __half22float2(hx[3]);
#pragma unroll
        for (int r = 0; r < Rr; r++) {
            uint4 a = *(const uint4*)&Aw[r * Kc + k];
            const half2* ha = (const half2*)&a;
            float2 fa0 = __half22float2(ha[0]);
            float2 fa1 = __half22float2(ha[1]);
            float2 fa2 = __half22float2(ha[2]);
            float2 fa3 = __half22float2(ha[3]);
            acc[r] += fx0.x * fa0.x + fx0.y * fa0.y
                    + fx1.x * fa1.x + fx1.y * fa1.y
                    + fx2.x * fa2.x + fx2.y * fa2.y
                    + fx3.x * fa3.x + fx3.y * fa3.y;
        }
    }
#pragma unroll
    for (int r = 0; r < Rr; r++) {
        float v = acc[r];
#pragma unroll
        for (int off = 16; off; off >>= 1) v += __shfl_xor_sync(0xffffffffu, v, off);
        acc[r] = v;
    }
    if (lane == 0) {
        __half tmp[16];
#pragma unroll
        for (int r = 0; r < Rr; r++) tmp[pperm(r)] = __float2half_rn(acc[r]);
        *(uint4*)&XA[(size_t)m * Rr]     = *(uint4*)&tmp[0];
        *(uint4*)&XA[(size_t)m * Rr + 8] = *(uint4*)&tmp[8];
    }
}

// ---------------------------------------------------------------------------
// fp16 GEMM (m16n8k16), cp.async double-buffered, LoRA folded as final stage:
//   out = [A | XA] @ [W | LBs]^T + bias
// Block 128x128, BK=64 (16+1 stages), 256 threads, 8 warps (2x4), warp 64x32.
// smem stride 80 halves (160B) -> all LDS.64 conflict-free.
// MODE 0 epilogue: q (xQSCALE) / k -> g_qk fp16 perm; v -> g_v transposed.
// MODE 1 epilogue: plain fp32 + bias.
// ---------------------------------------------------------------------------
#define GBK   64
#define GSTRH 80
#define GBN   128
#define GEMM_SMEM (2 * (2 * 128 * GSTRH) * 2)   // 81920 bytes

template <int MODE>
__global__ __launch_bounds__(256, 2)
void gemm_lora_f16(const __half* __restrict__ A, const __half* __restrict__ W,
                   const float* __restrict__ bias, const __half* __restrict__ XA,
                   const __half* __restrict__ LBs, float* __restrict__ outf,
                   __half* __restrict__ qk, __half* __restrict__ gv, int N)
{
    extern __shared__ __half smh[];
    __half* sA = smh;                           // [2][128][GSTRH]
    __half* sW = smh + 2 * 128 * GSTRH;         // [2][128][GSTRH]

    const int tid  = threadIdx.x;
    const int row0 = blockIdx.y * 128;
    const int col0 = blockIdx.x * GBN;
    const int lane = tid & 31, wid = tid >> 5;
    const int wm = (wid >> 2) * 64;
    const int wn = (wid & 3) * 32;
    const int g  = lane >> 2, tq = lane & 3;

    const int arow = tid >> 1;
    const int ahalf = (tid & 1) * 32;           // 64B half-row

    float acc[4][4][4];
#pragma unroll
    for (int mt = 0; mt < 4; mt++)
#pragma unroll
        for (int nt = 0; nt < 4; nt++)
#pragma unroll
            for (int i = 0; i < 4; i++) acc[mt][nt][i] = 0.f;

    const int NMAIN = Kc / GBK;     // 16
    const int NST   = NMAIN + 1;

    auto load_main = [&](int s, int buf) {
        const __half* pa = A + (size_t)(row0 + arow) * Kc + s * GBK + ahalf;
        uint32_t da = smem_u32(&sA[(buf * 128 + arow) * GSTRH + ahalf]);
        cp16(da,      pa);      cp16(da + 16, pa + 8);
        cp16(da + 32, pa + 16); cp16(da + 48, pa + 24);
        const __half* pw = W + (size_t)(col0 + arow) * Kc + s * GBK + ahalf;
        uint32_t dw = smem_u32(&sW[(buf * 128 + arow) * GSTRH + ahalf]);
        cp16(dw,      pw);      cp16(dw + 16, pw + 8);
        cp16(dw + 32, pw + 16); cp16(dw + 48, pw + 24);
    };
    auto load_lora = [&](int buf) {
        const int r = tid >> 1;
        if ((tid & 1) == 0) {
            const __half* pa = XA + (size_t)(row0 + r) * Rr;
            uint32_t da = smem_u32(&sA[(buf * 128 + r) * GSTRH]);
            cp16(da, pa); cp16(da + 16, pa + 8);
        } else {
            const __half* pw = LBs + (size_t)(col0 + r) * Rr;
            uint32_t dw = smem_u32(&sW[(buf * 128 + r) * GSTRH]);
            cp16(dw, pw); cp16(dw + 16, pw + 8);
        }
    };
    auto compute = [&](int buf, int nsteps) {
        const __half* bA = sA + (size_t)buf * 128 * GSTRH;
        const __half* bW = sW + (size_t)buf * 128 * GSTRH;
        for (int ks = 0; ks < nsteps; ks++) {
            const int ko = ks * 16 + tq * 4;
            unsigned af[4][4], bf[4][2];
#pragma unroll
            for (int mt = 0; mt < 4; mt++) {
                const __half* rp = &bA[(wm + mt * 16 + g) * GSTRH + ko];
                uint2 lo = *(const uint2*)rp;
                uint2 hi = *(const uint2*)(rp + 8 * GSTRH);
                af[mt][0] = lo.x; af[mt][2] = lo.y;
                af[mt][1] = hi.x; af[mt][3] = hi.y;
            }
#pragma unroll
            for (int nt = 0; nt < 4; nt++) {
                uint2 bb = *(const uint2*)&bW[(wn + nt * 8 + g) * GSTRH + ko];
                bf[nt][0] = bb.x; bf[nt][1] = bb.y;
            }
#pragma unroll
            for (int mt = 0; mt < 4; mt++)
#pragma unroll
                for (int nt = 0; nt < 4; nt++)
                    mma_f16(acc[mt][nt], af[mt], bf[nt][0], bf[nt][1]);
        }
    };

    load_main(0, 0);
    cp_commit();

    for (int s = 0; s < NST; s++) {
        const int cur = s & 1;
        const bool hn = (s + 1 < NST);
        if (hn) {
            if (s + 1 < NMAIN) load_main(s + 1, cur ^ 1);
            else               load_lora(cur ^ 1);
            cp_commit();
            cp_wait<1>();
        } else {
            cp_wait<0>();
        }
        __syncthreads();
        compute(cur, (s < NMAIN) ? 4 : 1);
        __syncthreads();
    }

    // epilogue
#pragma unroll
    for (int nt = 0; nt < 4; nt++) {
        const int n = col0 + wn + nt * 8 + 2 * tq;   // even
        const float b0 = bias[n], b1 = bias[n + 1];
#pragma unroll
        for (int mt = 0; mt < 4; mt++) {
            const int r = row0 + wm + mt * 16 + g;
            float v0 = acc[mt][nt][0] + b0, v1 = acc[mt][nt][1] + b1;
            float v2 = acc[mt][nt][2] + b0, v3 = acc[mt][nt][3] + b1;
            if (MODE == 1) {
                float2 lo; lo.x = v0; lo.y = v1;
                *(float2*)&outf[(size_t)r * N + n] = lo;
                float2 hi; hi.x = v2; hi.y = v3;
                *(float2*)&outf[(size_t)(r + 8) * N + n] = hi;
            } else {
                if (n < 2 * Cc) {
                    const float s125 = (n < Cc) ? QSCALE : 1.f;
                    half2 lo = __floats2half2_rn(v0 * s125, v1 * s125);
                    half2 hi = __floats2half2_rn(v2 * s125, v3 * s125);
                    const int base = n & ~15, pos = pperm(n & 15);
                    *(half2*)&qk[(size_t)r * 2048 + base + pos]       = lo;
                    *(half2*)&qk[(size_t)(r + 8) * 2048 + base + pos] = hi;
                } else {
                    const int dg = n - 2 * Cc;
                    const int hh = dg >> 6, dd = dg & 63;
                    const int bb = r >> 11, t = r & (Tc - 1);
                    const int tb = t & ~15, tp = pperm(t & 15);
                    __half* vr0 = &gv[(((size_t)(bb * NH + hh)) * HD + dd) * Tc + tb];
                    __half* vr1 = vr0 + Tc;
                    vr0[tp]     = __float2half_rn(v0);
                    vr0[tp + 2] = __float2half_rn(v2);
                    vr1[tp]     = __float2half_rn(v1);
                    vr1[tp + 2] = __float2half_rn(v3);
                }
            }
        }
    }
}

// ---------------------------------------------------------------------------
// Flash attention, fp16 m16n8k16, exp2-domain softmax (q pre-scaled by
// 0.125*log2e). K and V both double-buffered; prefetch distance 2; two
// barriers per kv-tile. 40KB smem, 4 blocks/SM.
// ---------------------------------------------------------------------------
#define KSTRH 80
#define ATTN_SMEM ((2 * 64 * KSTRH + 2 * 64 * KSTRH) * 2)

__global__ __launch_bounds__(128, 4)
void attn_f16(const __half* __restrict__ qk, const __half* __restrict__ gv,
              __half* __restrict__ yh)
{
    extern __shared__ __half smh[];
    __half* Ks = smh;                        // [2][64][KSTRH]
    __half* Vt = smh + 2 * 64 * KSTRH;       // [2][64][KSTRH]

    const int bid = blockIdx.x;
    const int qb  = (Tc / 64 - 1) - (bid >> 5);  // heavy blocks first
    const int bh  = bid & 31;
    const int b   = bh >> 4;
    const int h   = bh & 15;
    const int tid = threadIdx.x;
    const int lane = tid & 31, wid = tid >> 5;
    const int wm  = wid * 16;
    const int g   = lane >> 2, tq = lane & 3;
    const int qg0 = qb * 64;

    const __half* qbase = qk + (size_t)(b * Tc) * 2048 + h * 64;
    const __half* kbase = qbase + 1024;
    const __half* vhead = gv + ((size_t)(b * NH + h)) * HD * Tc;

    const int krow  = tid >> 1;
    const int khalf = (tid & 1) * 32;

    auto load_kv = [&](int jt, int buf) {
        const __half* pk = kbase + (size_t)(jt * 64 + krow) * 2048 + khalf;
        uint32_t dk = smem_u32(&Ks[(buf * 64 + krow) * KSTRH + khalf]);
        cp16(dk, pk);           cp16(dk + 16, pk + 8);
        cp16(dk + 32, pk + 16); cp16(dk + 48, pk + 24);
        const __half* pv = vhead + (size_t)krow * Tc + jt * 64 + khalf;
        uint32_t dv = smem_u32(&Vt[(buf * 64 + krow) * KSTRH + khalf]);
        cp16(dv, pv);           cp16(dv + 16, pv + 8);
        cp16(dv + 32, pv + 16); cp16(dv + 48, pv + 24);
    };

    load_kv(0, 0);
    cp_commit();
    if (qb >= 1) { load_kv(1, 1); cp_commit(); }

    // Q fragments from gmem (q already scaled by 0.125*log2e, d-permuted)
    unsigned qa[4][4];
    {
        const __half* q0 = qbase + (size_t)(qg0 + wm + g) * 2048;
        const __half* q1 = q0 + 8 * (size_t)2048;
#pragma unroll
        for (int kb = 0; kb < 4; kb++) {
            uint2 lo = *(const uint2*)&q0[kb * 16 + tq * 4];
            uint2 hi = *(const uint2*)&q1[kb * 16 + tq * 4];
            qa[kb][0] = lo.x; qa[kb][2] = lo.y;
            qa[kb][1] = hi.x; qa[kb][3] = hi.y;
        }
    }

    float o[8][4];
#pragma unroll
    for (int nt = 0; nt < 8; nt++)
#pragma unroll
        for (int i = 0; i < 4; i++) o[nt][i] = 0.f;
    float m_lo = -INFINITY, m_hi = -INFINITY, l_lo = 0.f, l_hi = 0.f;

    const int r_lo = qg0 + wm + g;
    const int r_hi = r_lo + 8;

    for (int jt = 0; jt <= qb; jt++) {
        const int cur = jt & 1;
        if (jt < qb) cp_wait<1>(); else cp_wait<0>();
        __syncthreads();   // K/V(jt) visible to all

        const __half* bK = Ks + (size_t)cur * 64 * KSTRH;
        const __half* bV = Vt + (size_t)cur * 64 * KSTRH;

        // S = Q @ K^T (exp2 domain)
        float sc[8][4];
#pragma unroll
        for (int nt = 0; nt < 8; nt++) {
#pragma unroll
            for (int i = 0; i < 4; i++) sc[nt][i] = 0.f;
            const __half* kr = &bK[(nt * 8 + g) * KSTRH + tq * 4];
#pragma unroll
            for (int kb = 0; kb < 4; kb++) {
                uint2 bb = *(const uint2*)&kr[kb * 16];
                mma_f16(sc[nt], qa[kb], bb.x, bb.y);
            }
        }

        // causal mask on the diagonal tile
        if (jt == qb) {
#pragma unroll
            for (int nt = 0; nt < 8; nt++) {
                const int c = qg0 + nt * 8 + 2 * tq;
                if (c     > r_lo) sc[nt][0] = -INFINITY;
                if (c + 1 > r_lo) sc[nt][1] = -INFINITY;
                if (c     > r_hi) sc[nt][2] = -INFINITY;
                if (c + 1 > r_hi) sc[nt][3] = -INFINITY;
            }
        }

        // online softmax in exp2 domain
        float tmax_lo = -INFINITY, tmax_hi = -INFINITY;
#pragma unroll
        for (int nt = 0; nt < 8; nt++) {
            tmax_lo = fmaxf(tmax_lo, fmaxf(sc[nt][0], sc[nt][1]));
            tmax_hi = fmaxf(tmax_hi, fmaxf(sc[nt][2], sc[nt][3]));
        }
        tmax_lo = fmaxf(tmax_lo, __shfl_xor_sync(0xffffffffu, tmax_lo, 1));
        tmax_lo = fmaxf(tmax_lo, __shfl_xor_sync(0xffffffffu, tmax_lo, 2));
        tmax_hi = fmaxf(tmax_hi, __shfl_xor_sync(0xffffffffu, tmax_hi, 1));
        tmax_hi = fmaxf(tmax_hi, __shfl_xor_sync(0xffffffffu, tmax_hi, 2));

        const float mn_lo = fmaxf(m_lo, tmax_lo);
        const float mn_hi = fmaxf(m_hi, tmax_hi);
        const float corr_lo = fex2(m_lo - mn_lo);
        const float corr_hi = fex2(m_hi - mn_hi);
        m_lo = mn_lo; m_hi = mn_hi;

        float ls_lo = 0.f, ls_hi = 0.f;
#pragma unroll
        for (int nt = 0; nt < 8; nt++) {
            sc[nt][0] = fex2(sc[nt][0] - mn_lo);
            sc[nt][1] = fex2(sc[nt][1] - mn_lo);
            sc[nt][2] = fex2(sc[nt][2] - mn_hi);
            sc[nt][3] = fex2(sc[nt][3] - mn_hi);
            ls_lo += sc[nt][0] + sc[nt][1];
            ls_hi += sc[nt][2] + sc[nt][3];
        }
        ls_lo += __shfl_xor_sync(0xffffffffu, ls_lo, 1);
        ls_lo += __shfl_xor_sync(0xffffffffu, ls_lo, 2);
        ls_hi += __shfl_xor_sync(0xffffffffu, ls_hi, 1);
        ls_hi += __shfl_xor_sync(0xffffffffu, ls_hi, 2);
        l_lo = l_lo * corr_lo + ls_lo;
        l_hi = l_hi * corr_hi + ls_hi;

#pragma unroll
        for (int nt = 0; nt < 8; nt++) {
            o[nt][0] *= corr_lo; o[nt][1] *= corr_lo;
            o[nt][2] *= corr_hi; o[nt][3] *= corr_hi;
        }

        // O += P @ V. PV A-frags = register packs of S C-frags (layout match).
#pragma unroll
        for (int kb = 0; kb < 4; kb++) {
            unsigned pa[4];
            pa[0] = h2u(__floats2half2_rn(sc[2*kb][0],   sc[2*kb][1]));
            pa[1] = h2u(__floats2half2_rn(sc[2*kb][2],   sc[2*kb][3]));
            pa[2] = h2u(__floats2half2_rn(sc[2*kb+1][0], sc[2*kb+1][1]));
            pa[3] = h2u(__floats2half2_rn(sc[2*kb+1][2], sc[2*kb+1][3]));
            const int ko = kb * 16 + tq * 4;
#pragma unroll
            for (int nt = 0; nt < 8; nt++) {
                uint2 vv = *(const uint2*)&bV[(nt * 8 + g) * KSTRH + ko];
                mma_f16(o[nt], pa, vv.x, vv.y);
            }
        }
        __syncthreads();   // all warps done reading buf cur
        if (jt + 2 <= qb) { load_kv(jt + 2, cur); cp_commit(); }
    }

    // write y (fp16, d pair-permuted) for GEMM2 / lora_a_h
    const float inv_lo = 1.f / l_lo;
    const float inv_hi = 1.f / l_hi;
#pragma unroll
    for (int nt = 0; nt < 8; nt++) {
        const int c = h * 64 + nt * 8 + 2 * tq;     // even
        const int base = c & ~15, pos = pperm(c & 15);
        half2 lo = __floats2half2_rn(o[nt][0] * inv_lo, o[nt][1] * inv_lo);
        half2 hi = __floats2half2_rn(o[nt][2] * inv_hi, o[nt][3] * inv_hi);
        *(half2*)&yh[(size_t)(b * Tc + r_lo) * Cc + base + pos] = lo;
        *(half2*)&yh[(size_t)(b * Tc + r_hi) * Cc + base + pos] = hi;
    }
}

// ---------------------------------------------------------------------------
// Launcher
// ---------------------------------------------------------------------------
extern "C" void kernel_launch(void* const* d_in, const int* in_sizes, int n_in,
                              void* d_out, int out_size)
{
    const float* x        = (const float*)d_in[0];
    const float* w_attn   = (const float*)d_in[1];
    const float* b_attn   = (const float*)d_in[2];
    const float* la_attn  = (const float*)d_in[3];
    const float* lb_attn  = (const float*)d_in[4];
    const float* w_proj   = (const float*)d_in[5];
    const float* b_proj   = (const float*)d_in[6];
    const float* la_proj  = (const float*)d_in[7];
    const float* lb_proj  = (const float*)d_in[8];
    float* out            = (float*)d_out;

    __half *qk, *gv, *yh, *xa, *ya, *xh, *w1h, *w2h, *lb1h, *lb2h, *la1h, *la2h;
    cudaGetSymbolAddress((void**)&qk,   g_qk);
    cudaGetSymbolAddress((void**)&gv,   g_v);
    cudaGetSymbolAddress((void**)&yh,   g_y);
    cudaGetSymbolAddress((void**)&xa,   g_xa);
    cudaGetSymbolAddress((void**)&ya,   g_ya);
    cudaGetSymbolAddress((void**)&xh,   g_xh);
    cudaGetSymbolAddress((void**)&w1h,  g_w1h);
    cudaGetSymbolAddress((void**)&w2h,  g_w2h);
    cudaGetSymbolAddress((void**)&lb1h, g_lb1h);
    cudaGetSymbolAddress((void**)&lb2h, g_lb2h);
    cudaGetSymbolAddress((void**)&la1h, g_la1h);
    cudaGetSymbolAddress((void**)&la2h, g_la2h);

    cudaFuncSetAttribute(gemm_lora_f16<0>,
                         cudaFuncAttributeMaxDynamicSharedMemorySize, GEMM_SMEM);
    cudaFuncSetAttribute(gemm_lora_f16<1>,
                         cudaFuncAttributeMaxDynamicSharedMemorySize, GEMM_SMEM);
    cudaFuncSetAttribute(attn_f16,
                         cudaFuncAttributeMaxDynamicSharedMemorySize, ATTN_SMEM);

    // 0. fp16 + pair-perm pre-conversion
    prep_kernel<<<2048, 256>>>((const float4*)x, (const float4*)w_attn,
                               (const float4*)w_proj, (const float4*)lb_attn,
                               (const float4*)lb_proj, (const float4*)la_attn,
                               (const float4*)la_proj,
                               xh, w1h, w2h, lb1h, lb2h, la1h, la2h);

    // 1. xa = x @ A_attn^T (fp16, matching perms)
    lora_a_h<<<Mtot / 8, 256>>>(xh, la1h, xa);

    // 2. q(xQSCALE),k -> g_qk; v -> g_v transposed
    {
        dim3 grid(N1 / GBN, Mtot / 128);
        gemm_lora_f16<0><<<grid, 256, GEMM_SMEM>>>(
            xh, w1h, b_attn, xa, lb1h, nullptr, qk, gv, N1);
    }

    // 3. attention -> y (fp16, perm)
    attn_f16<<<(Tc / 64) * Bc * NH, 128, ATTN_SMEM>>>(qk, gv, yh);

    // 4. ya = y @ A_proj^T (fp16, matching perms)
    lora_a_h<<<Mtot / 8, 256>>>(yh, la2h, ya);

    // 5. out = [y|ya] @ [W|LB*s]^T + b (fp32 output)
    {
        dim3 grid(Cc / GBN, Mtot / 128);
        gemm_lora_f16<1><<<grid, 256, GEMM_SMEM>>>(
            yh, w2h, b_proj, ya, lb2h, out, nullptr, nullptr, Cc);
    }
}